// round 15
// baseline (speedup 1.0000x reference)
#include <cuda_runtime.h>
#include <cuda_fp16.h>
#include <math.h>
#include <stdint.h>

#define D_MODEL 1024
#define NH      16
#define DK      64
#define NB      4
#define TGT     512
#define SRCL    256
#define NLAYER  8
#define FFDIM   4096
#define VOCAB   32000

typedef __half hf;

// ---------------- weight arena layout (elems) ---------------------------------
#define OFF_QKV  ((size_t)0)
#define OFF_SAO  ((size_t)25165824)
#define OFF_CAQ  ((size_t)33554432)
#define OFF_CAKV ((size_t)41943040)
#define OFF_CAO  ((size_t)58720256)
#define OFF_FF1  ((size_t)67108864)
#define OFF_FF2  ((size_t)100663296)
#define OFF_FC   ((size_t)134217728)
#define W_ELEMS  ((size_t)166985728)

// ---------------- scratch ----------------------------------------------------
__device__ float g_x   [NB*TGT*D_MODEL];
__device__ float g_tmp [NB*TGT*D_MODEL];
__device__ hf    g_xhi [NB*TGT*D_MODEL];
__device__ hf    g_xlo [NB*TGT*D_MODEL];
__device__ hf    g_ehi [NB*SRCL*D_MODEL];
__device__ hf    g_elo [NB*SRCL*D_MODEL];
__device__ hf    g_qkvh[NB*TGT*3*D_MODEL];
__device__ hf    g_qkvl[NB*TGT*3*D_MODEL];
__device__ hf    g_kvh [NB*SRCL*2*D_MODEL];
__device__ hf    g_kvl [NB*SRCL*2*D_MODEL];
__device__ hf    g_ahi [NB*TGT*FFDIM];
__device__ hf    g_alo [NB*TGT*FFDIM];
__device__ hf    g_w   [W_ELEMS];
__device__ float g_biasall[NLAYER*3072 + NLAYER*2048];

// ---------------- warp-MMA primitives ----------------------------------------
__device__ __forceinline__ void ldsm4(uint32_t* r, uint32_t addr) {
    asm volatile("ldmatrix.sync.aligned.m8n8.x4.shared.b16 {%0,%1,%2,%3}, [%4];"
                 : "=r"(r[0]), "=r"(r[1]), "=r"(r[2]), "=r"(r[3]) : "r"(addr));
}
__device__ __forceinline__ void ldsm4t(uint32_t* r, uint32_t addr) {
    asm volatile("ldmatrix.sync.aligned.m8n8.x4.trans.shared.b16 {%0,%1,%2,%3}, [%4];"
                 : "=r"(r[0]), "=r"(r[1]), "=r"(r[2]), "=r"(r[3]) : "r"(addr));
}
__device__ __forceinline__ void mma16816(float* d, const uint32_t* a, const uint32_t* b) {
    asm volatile("mma.sync.aligned.m16n8k16.row.col.f32.f16.f16.f32 "
                 "{%0,%1,%2,%3}, {%4,%5,%6,%7}, {%8,%9}, {%0,%1,%2,%3};"
                 : "+f"(d[0]), "+f"(d[1]), "+f"(d[2]), "+f"(d[3])
                 : "r"(a[0]), "r"(a[1]), "r"(a[2]), "r"(a[3]), "r"(b[0]), "r"(b[1]));
}
__device__ __forceinline__ void cp16(uint32_t dst, const void* src) {
    asm volatile("cp.async.cg.shared.global [%0], [%1], 16;" :: "r"(dst), "l"(src) : "memory");
}
__device__ __forceinline__ void cp_commit() {
    asm volatile("cp.async.commit_group;" ::: "memory");
}
__device__ __forceinline__ void cp_waitg(int tail_rem) {
    if (tail_rem >= 3)      asm volatile("cp.async.wait_group 2;" ::: "memory");
    else if (tail_rem == 2) asm volatile("cp.async.wait_group 1;" ::: "memory");
    else                    asm volatile("cp.async.wait_group 0;" ::: "memory");
}
__device__ __forceinline__ uint32_t pkh(hf a, hf b) {
    __half2 t = __halves2half2(a, b);
    return *(uint32_t*)&t;
}

// ---------------- fused weight conversion ------------------------------------
struct ConvDescs {
    const float* src[11];
    long         start4[11];
    size_t       dst[11];
    int          mode[11];
    int          off[11];
};

__global__ __launch_bounds__(256) void conv_all(ConvDescs D,
                                                hf* __restrict__ Ht,
                                                long total4) {
    long stride = (long)gridDim.x * blockDim.x;
    for (long i = (long)blockIdx.x * blockDim.x + threadIdx.x; i < total4; i += stride) {
        int seg = 0;
        #pragma unroll
        for (int j = 1; j < 11; j++) if (i >= D.start4[j]) seg = j;
        long local = i - D.start4[seg];
        float4 v = ((const float4*)D.src[seg])[local];
        size_t o;
        int mode = D.mode[seg];
        if (mode == 0) {
            o = D.dst[seg] + (size_t)local * 4;
        } else {
            long l    = local >> 18;
            long rem  = local & ((1L << 18) - 1);
            long k    = rem >> 8;
            long colc = (rem & 255) << 2;
            if (mode == 1)
                o = D.dst[seg] + (size_t)l * 3145728 + (size_t)k * 3072 + D.off[seg] + colc;
            else
                o = D.dst[seg] + (size_t)l * 2097152 + (size_t)k * 2048 + D.off[seg] + colc;
        }
        *(__half2*)(Ht + o)     = __floats2half2_rn(v.x, v.y);
        *(__half2*)(Ht + o + 2) = __floats2half2_rn(v.z, v.w);
    }
}

__global__ void bias_all(const float* __restrict__ q, const float* __restrict__ k,
                         const float* __restrict__ v, const float* __restrict__ ck,
                         const float* __restrict__ cv, float* __restrict__ d) {
    int i = blockIdx.x * blockDim.x + threadIdx.x;
    if (i < NLAYER * 3072) {
        int l = i / 3072, j = i - l * 3072;
        d[i] = (j < 1024) ? q[l*1024 + j]
             : (j < 2048) ? k[l*1024 + j - 1024]
                          : v[l*1024 + j - 2048];
    } else {
        int r = i - NLAYER * 3072;
        int l = r / 2048, j = r - l * 2048;
        d[i] = (j < 1024) ? ck[l*1024 + j] : cv[l*1024 + j - 1024];
    }
}

// ---------------- 128-row-tile GEMM (TERMS=2 or 1), 2x4 warp grid, 4 stages ---
// MMA order: all-hi pass (16 distinct accs) then all-lo pass -> RAW distance 16.
template<int TERMS>
__device__ __forceinline__ void load_stage(uint32_t stb,
        const hf* __restrict__ Ahp, const hf* __restrict__ Alp, int lda,
        const hf* __restrict__ Bp, int ldb,
        int k0, int tid) {
    const uint32_t BOFF = (TERMS == 2) ? 16384u : 8192u;
    {
        int r0 = tid >> 2, c0 = tid & 3;
        const hf* a = Ahp + k0 + c0 * 8;
        #pragma unroll
        for (int h2 = 0; h2 < 2; h2++) {
            int row = r0 + h2 * 64;
            uint32_t d = stb + row * 64 + ((c0 ^ (row & 3)) << 4);
            cp16(d, a + (size_t)row * lda);
        }
        if (TERMS == 2) {
            const hf* a2 = Alp + k0 + c0 * 8;
            #pragma unroll
            for (int h2 = 0; h2 < 2; h2++) {
                int row = r0 + h2 * 64;
                uint32_t d = stb + 8192 + row * 64 + ((c0 ^ (row & 3)) << 4);
                cp16(d, a2 + (size_t)row * lda);
            }
        }
    }
    {
        int r0 = tid >> 4, c = tid & 15;
        const hf* b = Bp + c * 8;
        #pragma unroll
        for (int h2 = 0; h2 < 2; h2++) {
            int r = r0 + h2 * 16;
            uint32_t d = stb + BOFF + r * 256 + ((c ^ (r & 7)) << 4);
            cp16(d, b + (size_t)(k0 + r) * ldb);
        }
    }
    cp_commit();
}

template<int MODE, int TERMS>
__global__ __launch_bounds__(256, 2)
void mma_gemm(const hf* __restrict__ Ah, const hf* __restrict__ Al,
              const hf* __restrict__ B,
              const float* __restrict__ bias,
              float* __restrict__ C, hf* __restrict__ Chi, hf* __restrict__ Clo,
              int M, int N, int K, int ldb, int ldc)
{
    extern __shared__ char smem[];
    const uint32_t SSZ  = (TERMS == 2) ? 24576u : 16384u;
    const uint32_t BOFF = (TERMS == 2) ? 16384u : 8192u;
    uint32_t sbase = (uint32_t)__cvta_generic_to_shared(smem);
    int tid = threadIdx.x, lane = tid & 31, wid = tid >> 5;
    int wm = wid & 1, wn = wid >> 1;           // 2 (M) x 4 (N) warp grid
    int bm = blockIdx.x * 128, bn = blockIdx.y * 128;

    const hf* pAh = Ah + (size_t)bm * K;
    const hf* pAl = Al + (size_t)bm * K;
    const hf* pB  = B + bn;

    float acc[4][4][4];
    #pragma unroll
    for (int a = 0; a < 4; a++)
        #pragma unroll
        for (int b2 = 0; b2 < 4; b2++)
            #pragma unroll
            for (int d = 0; d < 4; d++) acc[a][b2][d] = 0.f;

    const int NCH = K >> 5;
    load_stage<TERMS>(sbase,           pAh, pAl, K, pB, ldb, 0,  tid);
    load_stage<TERMS>(sbase + SSZ,     pAh, pAl, K, pB, ldb, 32, tid);
    load_stage<TERMS>(sbase + 2 * SSZ, pAh, pAl, K, pB, ldb, 64, tid);

    int a_r  = wm * 64 + (lane & 15);
    int a_ck = (lane >> 4) & 1;
    int b_rr = ((lane >> 3) & 1) * 8 + (lane & 7);
    int b_cc = wn * 4 + (lane >> 4);

    for (int c = 0; c < NCH; c++) {
        cp_waitg(NCH - c);
        __syncthreads();
        if (c + 3 < NCH)
            load_stage<TERMS>(sbase + ((c + 3) & 3) * SSZ, pAh, pAl, K, pB, ldb,
                              (c + 3) << 5, tid);

        uint32_t stb = sbase + (c & 3) * SSZ;
        #pragma unroll
        for (int k16 = 0; k16 < 2; k16++) {
            uint32_t a_hi[4][4], a_lo[4][4];
            #pragma unroll
            for (int mf = 0; mf < 4; mf++) {
                int row = a_r + mf * 16;
                int ck  = k16 * 2 + a_ck;
                uint32_t addr = stb + row * 64 + ((ck ^ (row & 3)) << 4);
                ldsm4(a_hi[mf], addr);
                if (TERMS == 2) ldsm4(a_lo[mf], addr + 8192);
            }
            int rr = k16 * 16 + b_rr;
            uint32_t bv[2][4];
            #pragma unroll
            for (int np2 = 0; np2 < 2; np2++) {
                int cc = b_cc + np2 * 2;
                ldsm4t(bv[np2], stb + BOFF + rr * 256 + ((cc ^ (rr & 7)) << 4));
            }
            // hi pass: 16 MMAs, 16 distinct accumulators
            #pragma unroll
            for (int np2 = 0; np2 < 2; np2++)
                #pragma unroll
                for (int mf = 0; mf < 4; mf++) {
                    mma16816(acc[mf][np2*2],   a_hi[mf], bv[np2]);
                    mma16816(acc[mf][np2*2+1], a_hi[mf], bv[np2] + 2);
                }
            // lo pass
            if (TERMS == 2) {
                #pragma unroll
                for (int np2 = 0; np2 < 2; np2++)
                    #pragma unroll
                    for (int mf = 0; mf < 4; mf++) {
                        mma16816(acc[mf][np2*2],   a_lo[mf], bv[np2]);
                        mma16816(acc[mf][np2*2+1], a_lo[mf], bv[np2] + 2);
                    }
            }
        }
    }

    __syncthreads();

    #pragma unroll
    for (int mf = 0; mf < 4; mf++) {
        int row0 = bm + wm * 64 + mf * 16 + (lane >> 2);
        #pragma unroll
        for (int nf = 0; nf < 4; nf++) {
            int col = bn + wn * 32 + nf * 8 + ((lane & 3) << 1);
            float bb0 = bias[col], bb1 = bias[col + 1];
            float v0 = acc[mf][nf][0] + bb0, v1 = acc[mf][nf][1] + bb1;
            float v2 = acc[mf][nf][2] + bb0, v3 = acc[mf][nf][3] + bb1;
            if (MODE == 2) {
                v0 = fmaxf(v0, 0.f); v1 = fmaxf(v1, 0.f);
                v2 = fmaxf(v2, 0.f); v3 = fmaxf(v3, 0.f);
            }
            if (MODE == 0) {
                float2 o0; o0.x = v0; o0.y = v1;
                float2 o1; o1.x = v2; o1.y = v3;
                *(float2*)(C + (size_t)row0 * ldc + col) = o0;
                *(float2*)(C + (size_t)(row0 + 8) * ldc + col) = o1;
            } else {
                hf h0 = __float2half_rn(v0), h1 = __float2half_rn(v1);
                hf h2 = __float2half_rn(v2), h3 = __float2half_rn(v3);
                *(__half2*)(Chi + (size_t)row0 * ldc + col)       = __halves2half2(h0, h1);
                *(__half2*)(Chi + (size_t)(row0 + 8) * ldc + col) = __halves2half2(h2, h3);
                *(__half2*)(Clo + (size_t)row0 * ldc + col) =
                    __floats2half2_rn(v0 - __half2float(h0), v1 - __half2float(h1));
                *(__half2*)(Clo + (size_t)(row0 + 8) * ldc + col) =
                    __floats2half2_rn(v2 - __half2float(h2), v3 - __half2float(h3));
            }
        }
    }
}

#define GEMM_SMEM2 (4*24576)
#define GEMM_SMEM1 (4*16384)

// ---------------- 64-row-tile GEMM, 4 stages ----------------------------------
#define GEMM_SMEM64 (4*16384)

__device__ __forceinline__ void load_stage64(uint32_t stb,
        const hf* __restrict__ Ahp, const hf* __restrict__ Alp, int lda,
        const hf* __restrict__ Bp, int ldb,
        int k0, int tid) {
    {
        int r0 = tid >> 2, c0 = tid & 3;
        uint32_t d = stb + r0 * 64 + ((c0 ^ (r0 & 3)) << 4);
        cp16(d,        Ahp + k0 + c0 * 8 + (size_t)r0 * lda);
        cp16(d + 4096, Alp + k0 + c0 * 8 + (size_t)r0 * lda);
    }
    {
        int r0 = tid >> 4, c = tid & 15;
        const hf* b = Bp + c * 8;
        #pragma unroll
        for (int h2 = 0; h2 < 2; h2++) {
            int r = r0 + h2 * 16;
            uint32_t d = stb + 8192 + r * 256 + ((c ^ (r & 7)) << 4);
            cp16(d, b + (size_t)(k0 + r) * ldb);
        }
    }
    cp_commit();
}

template<int MODE>
__global__ __launch_bounds__(256, 2)
void mma_gemm64(const hf* __restrict__ Ah, const hf* __restrict__ Al,
                const hf* __restrict__ B,
                const float* __restrict__ bias,
                float* __restrict__ C, hf* __restrict__ Chi, hf* __restrict__ Clo,
                int M, int N, int K, int ldb, int ldc)
{
    extern __shared__ char smem[];
    const uint32_t SSZ = 16384u, BOFF = 8192u;
    uint32_t sbase = (uint32_t)__cvta_generic_to_shared(smem);
    int tid = threadIdx.x, lane = tid & 31, wid = tid >> 5;
    int wm = wid & 1, wn = wid >> 1;
    int bm = blockIdx.x * 64, bn = blockIdx.y * 128;

    const hf* pAh = Ah + (size_t)bm * K;
    const hf* pAl = Al + (size_t)bm * K;
    const hf* pB  = B + bn;

    float acc[2][4][4];
    #pragma unroll
    for (int a = 0; a < 2; a++)
        #pragma unroll
        for (int b2 = 0; b2 < 4; b2++)
            #pragma unroll
            for (int d = 0; d < 4; d++) acc[a][b2][d] = 0.f;

    const int NCH = K >> 5;
    load_stage64(sbase,           pAh, pAl, K, pB, ldb, 0,  tid);
    load_stage64(sbase + SSZ,     pAh, pAl, K, pB, ldb, 32, tid);
    load_stage64(sbase + 2 * SSZ, pAh, pAl, K, pB, ldb, 64, tid);

    int a_r  = wm * 32 + (lane & 15);
    int a_ck = (lane >> 4) & 1;
    int b_rr = ((lane >> 3) & 1) * 8 + (lane & 7);
    int b_cc = wn * 4 + (lane >> 4);

    for (int c = 0; c < NCH; c++) {
        cp_waitg(NCH - c);
        __syncthreads();
        if (c + 3 < NCH)
            load_stage64(sbase + ((c + 3) & 3) * SSZ, pAh, pAl, K, pB, ldb,
                         (c + 3) << 5, tid);

        uint32_t stb = sbase + (c & 3) * SSZ;
        #pragma unroll
        for (int k16 = 0; k16 < 2; k16++) {
            uint32_t a_hi[2][4], a_lo[2][4];
            #pragma unroll
            for (int mf = 0; mf < 2; mf++) {
                int row = a_r + mf * 16;
                int ck  = k16 * 2 + a_ck;
                uint32_t addr = stb + row * 64 + ((ck ^ (row & 3)) << 4);
                ldsm4(a_hi[mf], addr);
                ldsm4(a_lo[mf], addr + 4096);
            }
            int rr = k16 * 16 + b_rr;
            uint32_t bv[2][4];
            #pragma unroll
            for (int np2 = 0; np2 < 2; np2++) {
                int cc = b_cc + np2 * 2;
                ldsm4t(bv[np2], stb + BOFF + rr * 256 + ((cc ^ (rr & 7)) << 4));
            }
            // hi pass: 8 MMAs, 8 distinct accumulators
            #pragma unroll
            for (int np2 = 0; np2 < 2; np2++)
                #pragma unroll
                for (int mf = 0; mf < 2; mf++) {
                    mma16816(acc[mf][np2*2],   a_hi[mf], bv[np2]);
                    mma16816(acc[mf][np2*2+1], a_hi[mf], bv[np2] + 2);
                }
            // lo pass
            #pragma unroll
            for (int np2 = 0; np2 < 2; np2++)
                #pragma unroll
                for (int mf = 0; mf < 2; mf++) {
                    mma16816(acc[mf][np2*2],   a_lo[mf], bv[np2]);
                    mma16816(acc[mf][np2*2+1], a_lo[mf], bv[np2] + 2);
                }
        }
    }

    __syncthreads();

    #pragma unroll
    for (int mf = 0; mf < 2; mf++) {
        int row0 = bm + wm * 32 + mf * 16 + (lane >> 2);
        #pragma unroll
        for (int nf = 0; nf < 4; nf++) {
            int col = bn + wn * 32 + nf * 8 + ((lane & 3) << 1);
            float bb0 = bias[col], bb1 = bias[col + 1];
            float v0 = acc[mf][nf][0] + bb0, v1 = acc[mf][nf][1] + bb1;
            float v2 = acc[mf][nf][2] + bb0, v3 = acc[mf][nf][3] + bb1;
            if (MODE == 0) {
                float2 o0; o0.x = v0; o0.y = v1;
                float2 o1; o1.x = v2; o1.y = v3;
                *(float2*)(C + (size_t)row0 * ldc + col) = o0;
                *(float2*)(C + (size_t)(row0 + 8) * ldc + col) = o1;
            } else {
                hf h0 = __float2half_rn(v0), h1 = __float2half_rn(v1);
                hf h2 = __float2half_rn(v2), h3 = __float2half_rn(v3);
                *(__half2*)(Chi + (size_t)row0 * ldc + col)       = __halves2half2(h0, h1);
                *(__half2*)(Chi + (size_t)(row0 + 8) * ldc + col) = __halves2half2(h2, h3);
                *(__half2*)(Clo + (size_t)row0 * ldc + col) =
                    __floats2half2_rn(v0 - __half2float(h0), v1 - __half2float(h1));
                *(__half2*)(Clo + (size_t)(row0 + 8) * ldc + col) =
                    __floats2half2_rn(v2 - __half2float(h2), v3 - __half2float(h3));
            }
        }
    }
}

// ---------------- flash attention (fp16 2-term) -------------------------------
#define FLASH_SMEM 49152

template<bool CAUSAL>
__global__ __launch_bounds__(256)
void flash_attn(const hf* __restrict__ Qh, const hf* __restrict__ Ql, int ldq, int qoff,
                const hf* __restrict__ Ks, int ldk, int koff,
                const hf* __restrict__ Vs, int ldv, int voff,
                const int* __restrict__ tgt,
                hf* __restrict__ Oh, hf* __restrict__ Ol, int ldo,
                int Sq, int Sk)
{
    extern __shared__ char sm[];
    uint32_t sb = (uint32_t)__cvta_generic_to_shared(sm);
    int tid = threadIdx.x, lane = tid & 31, w = tid >> 5;
    int bh = blockIdx.y, b = bh >> 4, h = bh & 15;
    int q0 = (CAUSAL ? (gridDim.x - 1 - blockIdx.x) : blockIdx.x) * 128;

    {
        const hf* qh = Qh + (size_t)(b * Sq + q0) * ldq + qoff + h * 64;
        const hf* ql = Ql + (size_t)(b * Sq + q0) * ldq + qoff + h * 64;
        #pragma unroll
        for (int i = 0; i < 4; i++) {
            int idx = tid + i * 256;
            int row = idx >> 3, c = idx & 7;
            uint32_t off = row * 128 + ((c ^ (row & 7)) << 4);
            *(uint4*)(sm + off)         = *(const uint4*)(qh + (size_t)row * ldq + c * 8);
            *(uint4*)(sm + 16384 + off) = *(const uint4*)(ql + (size_t)row * ldq + c * 8);
        }
    }

    int rq = lane >> 2;
    int qrow0 = q0 + w * 16 + rq;
    int qrow1 = qrow0 + 8;
    bool pad0 = false, pad1 = false;
    if (CAUSAL) {
        pad0 = (tgt[b * Sq + qrow0] == 0);
        pad1 = (tgt[b * Sq + qrow1] == 0);
    }

    float O[8][4];
    #pragma unroll
    for (int i = 0; i < 8; i++)
        #pragma unroll
        for (int j = 0; j < 4; j++) O[i][j] = 0.f;
    float m0 = -1e30f, m1 = -1e30f, s0 = 0.f, s1 = 0.f;

    int kend = CAUSAL ? (q0 + 128) : Sk;

    for (int k0 = 0; k0 < kend; k0 += 64) {
        __syncthreads();
        {
            const hf* srcs[2] = {
                Ks + (size_t)(b * Sk + k0) * ldk + koff + h * 64,
                Vs + (size_t)(b * Sk + k0) * ldv + voff + h * 64 };
            int lds[2] = { ldk, ldv };
            uint32_t dsts[2] = { 32768u, 40960u };
            #pragma unroll
            for (int t = 0; t < 2; t++) {
                #pragma unroll
                for (int i = 0; i < 2; i++) {
                    int idx = tid + i * 256;
                    int row = idx >> 3, c = idx & 7;
                    *(uint4*)(sm + dsts[t] + row * 128 + ((c ^ (row & 7)) << 4)) =
                        *(const uint4*)(srcs[t] + (size_t)row * lds[t] + c * 8);
                }
            }
        }
        __syncthreads();

        float S[8][4];
        #pragma unroll
        for (int i = 0; i < 8; i++)
            #pragma unroll
            for (int j = 0; j < 4; j++) S[i][j] = 0.f;

        #pragma unroll
        for (int ks = 0; ks < 4; ks++) {
            int arow = w * 16 + (lane & 15);
            int ac = ks * 2 + ((lane >> 4) & 1);
            uint32_t qa = sb + arow * 128 + ((ac ^ (arow & 7)) << 4);
            uint32_t ah[4], al[4];
            ldsm4(ah, qa);
            ldsm4(al, qa + 16384);
            #pragma unroll
            for (int np = 0; np < 4; np++) {
                int brow = np * 16 + (lane & 7) + ((lane >> 4) & 1) * 8;
                int bc = ks * 2 + ((lane >> 3) & 1);
                uint32_t ka = sb + 32768 + brow * 128 + ((bc ^ (brow & 7)) << 4);
                uint32_t kb[4];
                ldsm4(kb, ka);
                mma16816(S[np*2],   ah, kb);     mma16816(S[np*2+1],   ah, kb + 2);
                mma16816(S[np*2],   al, kb);     mma16816(S[np*2+1],   al, kb + 2);
            }
        }

        #pragma unroll
        for (int nt = 0; nt < 8; nt++) {
            int col = k0 + nt * 8 + 2 * (lane & 3);
            #pragma unroll
            for (int e = 0; e < 4; e++) S[nt][e] *= 0.125f;
            if (CAUSAL && k0 >= q0) {
                if (col     > qrow0) S[nt][0] = -1e9f;
                if (col + 1 > qrow0) S[nt][1] = -1e9f;
                if (col     > qrow1) S[nt][2] = -1e9f;
                if (col + 1 > qrow1) S[nt][3] = -1e9f;
            }
            if (CAUSAL) {
                if (pad0) { S[nt][0] = -1e9f; S[nt][1] = -1e9f; }
                if (pad1) { S[nt][2] = -1e9f; S[nt][3] = -1e9f; }
            }
        }

        float mx0 = -1e30f, mx1 = -1e30f;
        #pragma unroll
        for (int nt = 0; nt < 8; nt++) {
            mx0 = fmaxf(mx0, fmaxf(S[nt][0], S[nt][1]));
            mx1 = fmaxf(mx1, fmaxf(S[nt][2], S[nt][3]));
        }
        mx0 = fmaxf(mx0, __shfl_xor_sync(0xffffffffu, mx0, 1));
        mx0 = fmaxf(mx0, __shfl_xor_sync(0xffffffffu, mx0, 2));
        mx1 = fmaxf(mx1, __shfl_xor_sync(0xffffffffu, mx1, 1));
        mx1 = fmaxf(mx1, __shfl_xor_sync(0xffffffffu, mx1, 2));
        float mn0 = fmaxf(m0, mx0), mn1 = fmaxf(m1, mx1);
        float al0 = __expf(m0 - mn0), al1 = __expf(m1 - mn1);
        m0 = mn0; m1 = mn1;
        float ps0 = 0.f, ps1 = 0.f;
        #pragma unroll
        for (int nt = 0; nt < 8; nt++) {
            S[nt][0] = __expf(S[nt][0] - mn0);
            S[nt][1] = __expf(S[nt][1] - mn0);
            S[nt][2] = __expf(S[nt][2] - mn1);
            S[nt][3] = __expf(S[nt][3] - mn1);
            ps0 += S[nt][0] + S[nt][1];
            ps1 += S[nt][2] + S[nt][3];
        }
        ps0 += __shfl_xor_sync(0xffffffffu, ps0, 1);
        ps0 += __shfl_xor_sync(0xffffffffu, ps0, 2);
        ps1 += __shfl_xor_sync(0xffffffffu, ps1, 1);
        ps1 += __shfl_xor_sync(0xffffffffu, ps1, 2);
        s0 = s0 * al0 + ps0;
        s1 = s1 * al1 + ps1;
        #pragma unroll
        for (int nt = 0; nt < 8; nt++) {
            O[nt][0] *= al0; O[nt][1] *= al0;
            O[nt][2] *= al1; O[nt][3] *= al1;
        }

        #pragma unroll
        for (int ks = 0; ks < 4; ks++) {
            uint32_t pah[4], pal[4];
            #pragma unroll
            for (int half = 0; half < 2; half++) {
                float p0 = S[2*ks+half][0], p1 = S[2*ks+half][1];
                float p2 = S[2*ks+half][2], p3 = S[2*ks+half][3];
                hf ha = __float2half_rn(p0), hb = __float2half_rn(p1);
                hf hc = __float2half_rn(p2), hd = __float2half_rn(p3);
                pah[half*2 + 0] = pkh(ha, hb);
                pah[half*2 + 1] = pkh(hc, hd);
                __half2 lo01 = __floats2half2_rn(p0 - __half2float(ha), p1 - __half2float(hb));
                __half2 lo23 = __floats2half2_rn(p2 - __half2float(hc), p3 - __half2float(hd));
                pal[half*2 + 0] = *(uint32_t*)&lo01;
                pal[half*2 + 1] = *(uint32_t*)&lo23;
            }
            #pragma unroll
            for (int np = 0; np < 4; np++) {
                int rr = ks * 16 + ((lane >> 3) & 1) * 8 + (lane & 7);
                int cc = np * 2 + (lane >> 4);
                uint32_t va = sb + 40960 + rr * 128 + ((cc ^ (rr & 7)) << 4);
                uint32_t vb[4];
                ldsm4t(vb, va);
                mma16816(O[np*2],   pah, vb);     mma16816(O[np*2+1],   pah, vb + 2);
                mma16816(O[np*2],   pal, vb);     mma16816(O[np*2+1],   pal, vb + 2);
            }
        }
    }

    float inv0 = 1.f / s0, inv1 = 1.f / s1;
    size_t tr0 = (size_t)(b * Sq + qrow0) * ldo;
    size_t tr1 = (size_t)(b * Sq + qrow1) * ldo;
    #pragma unroll
    for (int nt = 0; nt < 8; nt++) {
        int col = h * 64 + nt * 8 + 2 * (lane & 3);
        float v0 = O[nt][0] * inv0, v1 = O[nt][1] * inv0;
        float v2 = O[nt][2] * inv1, v3 = O[nt][3] * inv1;
        hf h0 = __float2half_rn(v0), h1 = __float2half_rn(v1);
        hf h2 = __float2half_rn(v2), h3 = __float2half_rn(v3);
        *(__half2*)(Oh + tr0 + col) = __halves2half2(h0, h1);
        *(__half2*)(Oh + tr1 + col) = __halves2half2(h2, h3);
        *(__half2*)(Ol + tr0 + col) =
            __floats2half2_rn(v0 - __half2float(h0), v1 - __half2float(h1));
        *(__half2*)(Ol + tr1 + col) =
            __floats2half2_rn(v2 - __half2float(h2), v3 - __half2float(h3));
    }
}

// ---------------- positional encoding / embed --------------------------------
__device__ __forceinline__ float pe_val(int s, int d) {
    const float c = -0.0089944730195079f;
    int i2 = d & ~1;
    float freq = expf((float)i2 * c);
    float ang  = (float)s * freq;
    return (d & 1) ? cosf(ang) : sinf(ang);
}

__global__ void embed_pe(const int* __restrict__ tgt, const float* __restrict__ emb,
                         float* __restrict__ X, hf* __restrict__ Xh, hf* __restrict__ Xl) {
    int row = blockIdx.x;
    int s   = row % TGT;
    int tok = tgt[row];
    int t   = threadIdx.x;
    #pragma unroll
    for (int i = 0; i < 4; i++) {
        int d = t * 4 + i;
        float v = emb[(size_t)tok * D_MODEL + d] + pe_val(s, d);
        X[(size_t)row * D_MODEL + d] = v;
        hf h = __float2half_rn(v);
        Xh[(size_t)row * D_MODEL + d] = h;
        Xl[(size_t)row * D_MODEL + d] = __float2half_rn(v - __half2float(h));
    }
}

__global__ void src_pe(const float* __restrict__ src,
                       hf* __restrict__ Eh, hf* __restrict__ El) {
    int row = blockIdx.x;
    int s   = row % SRCL;
    int t   = threadIdx.x;
    #pragma unroll
    for (int i = 0; i < 4; i++) {
        int d = t * 4 + i;
        float v = src[(size_t)row * D_MODEL + d] + pe_val(s, d);
        hf h = __float2half_rn(v);
        Eh[(size_t)row * D_MODEL + d] = h;
        El[(size_t)row * D_MODEL + d] = __float2half_rn(v - __half2float(h));
    }
}

// ---------------- add + LayerNorm --------------------------------------------
__global__ __launch_bounds__(256) void add_ln(
    const float* __restrict__ X, const float* __restrict__ A,
    const float* __restrict__ G, const float* __restrict__ Bt,
    float* __restrict__ Y, hf* __restrict__ Yh, hf* __restrict__ Yl)
{
    __shared__ float red[8];
    __shared__ float bcast;
    int row = blockIdx.x;
    int t = threadIdx.x;
    int lane = t & 31, wid = t >> 5;

    float4 xv = *(const float4*)(X + (size_t)row * D_MODEL + t * 4);
    float4 av = *(const float4*)(A + (size_t)row * D_MODEL + t * 4);
    float v0 = xv.x + av.x, v1 = xv.y + av.y, v2 = xv.z + av.z, v3 = xv.w + av.w;

    float s = v0 + v1 + v2 + v3;
    #pragma unroll
    for (int o = 16; o; o >>= 1) s += __shfl_xor_sync(0xffffffffu, s, o);
    if (lane == 0) red[wid] = s;
    __syncthreads();
    if (t == 0) {
        float tot = 0.f;
        #pragma unroll
        for (int i = 0; i < 8; i++) tot += red[i];
        bcast = tot;
    }
    __syncthreads();
    float mean = bcast * (1.f / 1024.f);

    float d0 = v0 - mean, d1 = v1 - mean, d2 = v2 - mean, d3 = v3 - mean;
    s = d0 * d0 + d1 * d1 + d2 * d2 + d3 * d3;
    #pragma unroll
    for (int o = 16; o; o >>= 1) s += __shfl_xor_sync(0xffffffffu, s, o);
    if (lane == 0) red[wid] = s;
    __syncthreads();
    if (t == 0) {
        float tot = 0.f;
        #pragma unroll
        for (int i = 0; i < 8; i++) tot += red[i];
        bcast = tot;
    }
    __syncthreads();
    float rstd = rsqrtf(bcast * (1.f / 1024.f) + 1e-5f);

    int c = t * 4;
    float o0 = d0 * rstd * G[c + 0] + Bt[c + 0];
    float o1 = d1 * rstd * G[c + 1] + Bt[c + 1];
    float o2 = d2 * rstd * G[c + 2] + Bt[c + 2];
    float o3 = d3 * rstd * G[c + 3] + Bt[c + 3];
    float4 o; o.x = o0; o.y = o1; o.z = o2; o.w = o3;
    *(float4*)(Y + (size_t)row * D_MODEL + c) = o;
    hf h0 = __float2half_rn(o0), h1 = __float2half_rn(o1);
    hf h2 = __float2half_rn(o2), h3 = __float2half_rn(o3);
    *(__half2*)(Yh + (size_t)row * D_MODEL + c)     = __halves2half2(h0, h1);
    *(__half2*)(Yh + (size_t)row * D_MODEL + c + 2) = __halves2half2(h2, h3);
    *(__half2*)(Yl + (size_t)row * D_MODEL + c) =
        __floats2half2_rn(o0 - __half2float(h0), o1 - __half2float(h1));
    *(__half2*)(Yl + (size_t)row * D_MODEL + c + 2) =
        __floats2half2_rn(o2 - __half2float(h2), o3 - __half2float(h3));
}

// ---------------- host pointers ----------------------------------------------
static hf *h_xhi, *h_xlo, *h_ehi, *h_elo, *h_qkvh, *h_qkvl, *h_kvh, *h_kvl;
static hf *h_ahi, *h_alo, *h_w;
static float *h_x, *h_tmp, *h_bias;

// ---------------- orchestration ----------------------------------------------
extern "C" void kernel_launch(void* const* d_in, const int* in_sizes, int n_in,
                              void* d_out, int out_size) {
    bool layoutA = (in_sizes[3] == 8 * 1024 * 1024);

    const float* src = (const float*)d_in[0];
    const int*   tgt = (const int*)  d_in[1];
    const float* emb = (const float*)d_in[2];

    const float *sa_wq, *sa_bq, *sa_wk, *sa_bk, *sa_wv, *sa_bv, *sa_wo, *sa_bo;
    const float *ca_wq, *ca_bq, *ca_wk, *ca_bk, *ca_wv, *ca_bv, *ca_wo, *ca_bo;
    const float *w1, *b1, *w2, *b2;
    const float *n1g, *n1b, *n2g, *n2b, *n3g, *n3b;
    const float *fc_w, *fc_b;

    if (layoutA) {
        sa_wq = (const float*)d_in[3];  sa_bq = (const float*)d_in[4];
        sa_wk = (const float*)d_in[5];  sa_bk = (const float*)d_in[6];
        sa_wv = (const float*)d_in[7];  sa_bv = (const float*)d_in[8];
        sa_wo = (const float*)d_in[9];  sa_bo = (const float*)d_in[10];
        ca_wq = (const float*)d_in[11]; ca_bq = (const float*)d_in[12];
        ca_wk = (const float*)d_in[13]; ca_bk = (const float*)d_in[14];
        ca_wv = (const float*)d_in[15]; ca_bv = (const float*)d_in[16];
        ca_wo = (const float*)d_in[17]; ca_bo = (const float*)d_in[18];
        w1 = (const float*)d_in[19]; b1 = (const float*)d_in[20];
        w2 = (const float*)d_in[21]; b2 = (const float*)d_in[22];
        n1g = (const float*)d_in[23]; n1b = (const float*)d_in[24];
        n2g = (const float*)d_in[25]; n2b = (const float*)d_in[26];
        n3g = (const float*)d_in[27]; n3b = (const float*)d_in[28];
        fc_w = (const float*)d_in[29]; fc_b = (const float*)d_in[30];
    } else {
        fc_w = (const float*)d_in[3];  fc_b = (const float*)d_in[4];
        sa_wq = (const float*)d_in[5];  sa_bq = (const float*)d_in[6];
        sa_wk = (const float*)d_in[7];  sa_bk = (const float*)d_in[8];
        sa_wv = (const float*)d_in[9];  sa_bv = (const float*)d_in[10];
        sa_wo = (const float*)d_in[11]; sa_bo = (const float*)d_in[12];
        ca_wq = (const float*)d_in[13]; ca_bq = (const float*)d_in[14];
        ca_wk = (const float*)d_in[15]; ca_bk = (const float*)d_in[16];
        ca_wv = (const float*)d_in[17]; ca_bv = (const float*)d_in[18];
        ca_wo = (const float*)d_in[19]; ca_bo = (const float*)d_in[20];
        w1 = (const float*)d_in[21]; b1 = (const float*)d_in[22];
        w2 = (const float*)d_in[23]; b2 = (const float*)d_in[24];
        n1g = (const float*)d_in[25]; n2g = (const float*)d_in[26];
        n3g = (const float*)d_in[27]; n1b = (const float*)d_in[28];
        n2b = (const float*)d_in[29]; n3b = (const float*)d_in[30];
    }

    cudaGetSymbolAddress((void**)&h_x,    g_x);
    cudaGetSymbolAddress((void**)&h_tmp,  g_tmp);
    cudaGetSymbolAddress((void**)&h_xhi,  g_xhi);
    cudaGetSymbolAddress((void**)&h_xlo,  g_xlo);
    cudaGetSymbolAddress((void**)&h_ehi,  g_ehi);
    cudaGetSymbolAddress((void**)&h_elo,  g_elo);
    cudaGetSymbolAddress((void**)&h_qkvh, g_qkvh);
    cudaGetSymbolAddress((void**)&h_qkvl, g_qkvl);
    cudaGetSymbolAddress((void**)&h_kvh,  g_kvh);
    cudaGetSymbolAddress((void**)&h_kvl,  g_kvl);
    cudaGetSymbolAddress((void**)&h_ahi,  g_ahi);
    cudaGetSymbolAddress((void**)&h_alo,  g_alo);
    cudaGetSymbolAddress((void**)&h_w,    g_w);
    cudaGetSymbolAddress((void**)&h_bias, g_biasall);

    cudaFuncSetAttribute((const void*)mma_gemm<0,2>, cudaFuncAttributeMaxDynamicSharedMemorySize, GEMM_SMEM2);
    cudaFuncSetAttribute((const void*)mma_gemm<1,2>, cudaFuncAttributeMaxDynamicSharedMemorySize, GEMM_SMEM2);
    cudaFuncSetAttribute((const void*)mma_gemm<2,2>, cudaFuncAttributeMaxDynamicSharedMemorySize, GEMM_SMEM2);
    cudaFuncSetAttribute((const void*)mma_gemm<0,1>, cudaFuncAttributeMaxDynamicSharedMemorySize, GEMM_SMEM1);
    cudaFuncSetAttribute((const void*)mma_gemm64<0>, cudaFuncAttributeMaxDynamicSharedMemorySize, GEMM_SMEM64);
    cudaFuncSetAttribute((const void*)mma_gemm64<1>, cudaFuncAttributeMaxDynamicSharedMemorySize, GEMM_SMEM64);
    cudaFuncSetAttribute((const void*)flash_attn<true>,  cudaFuncAttributeMaxDynamicSharedMemorySize, FLASH_SMEM);
    cudaFuncSetAttribute((const void*)flash_attn<false>, cudaFuncAttributeMaxDynamicSharedMemorySize, FLASH_SMEM);

    const int Mx = NB * TGT;    // 2048
    const int Me = NB * SRCL;   // 1024

    {
        ConvDescs D;
        const long C2 = 2097152, C8 = 8388608;
        const float* srcs[11] = { sa_wq, sa_wk, sa_wv, sa_wo, ca_wq,
                                  ca_wk, ca_wv, ca_wo, w1, w2, fc_w };
        long starts[11] = { 0, C2, 2*C2, 3*C2, 4*C2, 5*C2, 6*C2, 7*C2,
                            8*C2, 8*C2 + C8, 8*C2 + 2*C8 };
        size_t dsts[11] = { OFF_QKV, OFF_QKV, OFF_QKV, OFF_SAO, OFF_CAQ,
                            OFF_CAKV, OFF_CAKV, OFF_CAO, OFF_FF1, OFF_FF2, OFF_FC };
        int modes[11] = { 1, 1, 1, 0, 0, 2, 2, 0, 0, 0, 0 };
        int offs[11]  = { 0, 1024, 2048, 0, 0, 0, 1024, 0, 0, 0, 0 };
        for (int i = 0; i < 11; i++) {
            D.src[i] = srcs[i]; D.start4[i] = starts[i];
            D.dst[i] = dsts[i]; D.mode[i] = modes[i]; D.off[i] = offs[i];
        }
        long total4 = 8*C2 + 2*C8 + 8192000;
        conv_all<<<4096, 256>>>(D, h_w, total4);
    }
    bias_all<<<160, 256>>>(sa_bq, sa_bk, sa_bv, ca_bk, ca_bv, h_bias);
    embed_pe<<<Mx, 256>>>(tgt, emb, h_x, h_xhi, h_xlo);

    bool did_src = false;

    for (int l = 0; l < NLAYER; l++) {
        const hf* Wqkv = h_w + OFF_QKV  + (size_t)l * 3145728;
        const hf* Wsao = h_w + OFF_SAO  + (size_t)l * 1048576;
        const hf* Wcaq = h_w + OFF_CAQ  + (size_t)l * 1048576;
        const hf* Wkv  = h_w + OFF_CAKV + (size_t)l * 2097152;
        const hf* Wcao = h_w + OFF_CAO  + (size_t)l * 1048576;
        const hf* Wf1  = h_w + OFF_FF1  + (size_t)l * 4194304;
        const hf* Wf2  = h_w + OFF_FF2  + (size_t)l * 4194304;

        // ---- self-attention ----
        mma_gemm<1,2><<<dim3(16, 24), 256, GEMM_SMEM2>>>(h_xhi, h_xlo, Wqkv,
            h_bias + (size_t)l * 3072, (float*)0, h_qkvh, h_qkvl, Mx, 3072, D_MODEL, 3072, 3072);
        if (!did_src) { src_pe<<<Me, 256>>>(src, h_ehi, h_elo); did_src = true; }
        flash_attn<true><<<dim3(4, 64), 256, FLASH_SMEM>>>(
            h_qkvh, h_qkvl, 3072, 0, h_qkvh, 3072, 1024,
            h_qkvh, 3072, 2048, tgt, h_ahi, h_alo, 1024, TGT, TGT);
        mma_gemm64<0><<<dim3(32, 8), 256, GEMM_SMEM64>>>(h_ahi, h_alo, Wsao,
            sa_bo + l*D_MODEL, h_tmp, (hf*)0, (hf*)0, Mx, D_MODEL, D_MODEL, D_MODEL, D_MODEL);
        add_ln<<<Mx, 256>>>(h_x, h_tmp, n1g + l*D_MODEL, n1b + l*D_MODEL, h_x, h_xhi, h_xlo);

        // ---- cross-attention ----
        mma_gemm64<1><<<dim3(32, 8), 256, GEMM_SMEM64>>>(h_xhi, h_xlo, Wcaq,
            ca_bq + l*D_MODEL, (float*)0, h_qkvh, h_qkvl, Mx, D_MODEL, D_MODEL, D_MODEL, D_MODEL);
        mma_gemm64<1><<<dim3(16, 16), 256, GEMM_SMEM64>>>(h_ehi, h_elo, Wkv,
            h_bias + NLAYER*3072 + (size_t)l * 2048, (float*)0, h_kvh, h_kvl, Me, 2048, D_MODEL, 2048, 2048);
        flash_attn<false><<<dim3(4, 64), 256, FLASH_SMEM>>>(
            h_qkvh, h_qkvl, 1024, 0, h_kvh, 2048, 0,
            h_kvh, 2048, 1024, (const int*)0, h_ahi, h_alo, 1024, TGT, SRCL);
        mma_gemm64<0><<<dim3(32, 8), 256, GEMM_SMEM64>>>(h_ahi, h_alo, Wcao,
            ca_bo + l*D_MODEL, h_tmp, (hf*)0, (hf*)0, Mx, D_MODEL, D_MODEL, D_MODEL, D_MODEL);
        add_ln<<<Mx, 256>>>(h_x, h_tmp, n2g + l*D_MODEL, n2b + l*D_MODEL, h_x, h_xhi, h_xlo);

        // ---- FFN ----
        mma_gemm<2,2><<<dim3(16, 32), 256, GEMM_SMEM2>>>(h_xhi, h_xlo, Wf1,
            b1 + (size_t)l*FFDIM, (float*)0, h_ahi, h_alo, Mx, FFDIM, D_MODEL, FFDIM, FFDIM);
        mma_gemm64<0><<<dim3(32, 8), 256, GEMM_SMEM64>>>(h_ahi, h_alo, Wf2,
            b2 + (size_t)l*D_MODEL, h_tmp, (hf*)0, (hf*)0, Mx, D_MODEL, FFDIM, D_MODEL, D_MODEL);
        add_ln<<<Mx, 256>>>(h_x, h_tmp, n3g + l*D_MODEL, n3b + l*D_MODEL, h_x, h_xhi, h_xlo);
    }

    // ---- final projection to vocab: single-term fp16 ----
    mma_gemm<0,1><<<dim3(16, 250), 256, GEMM_SMEM1>>>(h_xhi, h_xhi, h_w + OFF_FC,
        fc_b, (float*)d_out, (hf*)0, (hf*)0, Mx, VOCAB, D_MODEL, VOCAB, VOCAB);
    (void)n_in; (void)out_size;
}

// round 16
// speedup vs baseline: 1.0759x; 1.0759x over previous
#include <cuda_runtime.h>
#include <cuda_fp16.h>
#include <math.h>
#include <stdint.h>

#define D_MODEL 1024
#define NH      16
#define DK      64
#define NB      4
#define TGT     512
#define SRCL    256
#define NLAYER  8
#define FFDIM   4096
#define VOCAB   32000

typedef __half hf;

// ---------------- weight arena layout (elems) ---------------------------------
#define OFF_QKV  ((size_t)0)
#define OFF_SAO  ((size_t)25165824)
#define OFF_CAQ  ((size_t)33554432)
#define OFF_CAKV ((size_t)41943040)
#define OFF_CAO  ((size_t)58720256)
#define OFF_FF1  ((size_t)67108864)
#define OFF_FF2  ((size_t)100663296)
#define OFF_FC   ((size_t)134217728)
#define W_ELEMS  ((size_t)166985728)

// ---------------- scratch ----------------------------------------------------
__device__ float g_x   [NB*TGT*D_MODEL];
__device__ float g_tmp [NB*TGT*D_MODEL];
__device__ hf    g_xhi [NB*TGT*D_MODEL];
__device__ hf    g_xlo [NB*TGT*D_MODEL];
__device__ hf    g_ehi [NB*SRCL*D_MODEL];
__device__ hf    g_elo [NB*SRCL*D_MODEL];
__device__ hf    g_qkvh[NB*TGT*3*D_MODEL];
__device__ hf    g_qkvl[NB*TGT*3*D_MODEL];
__device__ hf    g_kvh [NB*SRCL*2*D_MODEL];
__device__ hf    g_kvl [NB*SRCL*2*D_MODEL];
__device__ hf    g_ahi [NB*TGT*FFDIM];
__device__ hf    g_alo [NB*TGT*FFDIM];
__device__ hf    g_w   [W_ELEMS];
__device__ float g_biasall[NLAYER*3072 + NLAYER*2048];

// ---------------- warp-MMA primitives ----------------------------------------
__device__ __forceinline__ void ldsm4(uint32_t* r, uint32_t addr) {
    asm volatile("ldmatrix.sync.aligned.m8n8.x4.shared.b16 {%0,%1,%2,%3}, [%4];"
                 : "=r"(r[0]), "=r"(r[1]), "=r"(r[2]), "=r"(r[3]) : "r"(addr));
}
__device__ __forceinline__ void ldsm4t(uint32_t* r, uint32_t addr) {
    asm volatile("ldmatrix.sync.aligned.m8n8.x4.trans.shared.b16 {%0,%1,%2,%3}, [%4];"
                 : "=r"(r[0]), "=r"(r[1]), "=r"(r[2]), "=r"(r[3]) : "r"(addr));
}
__device__ __forceinline__ void mma16816(float* d, const uint32_t* a, const uint32_t* b) {
    asm volatile("mma.sync.aligned.m16n8k16.row.col.f32.f16.f16.f32 "
                 "{%0,%1,%2,%3}, {%4,%5,%6,%7}, {%8,%9}, {%0,%1,%2,%3};"
                 : "+f"(d[0]), "+f"(d[1]), "+f"(d[2]), "+f"(d[3])
                 : "r"(a[0]), "r"(a[1]), "r"(a[2]), "r"(a[3]), "r"(b[0]), "r"(b[1]));
}
__device__ __forceinline__ void cp16(uint32_t dst, const void* src) {
    asm volatile("cp.async.cg.shared.global [%0], [%1], 16;" :: "r"(dst), "l"(src) : "memory");
}
__device__ __forceinline__ void cp_commit() {
    asm volatile("cp.async.commit_group;" ::: "memory");
}
__device__ __forceinline__ void cp_waitg(int tail_rem) {
    if (tail_rem >= 3)      asm volatile("cp.async.wait_group 2;" ::: "memory");
    else if (tail_rem == 2) asm volatile("cp.async.wait_group 1;" ::: "memory");
    else                    asm volatile("cp.async.wait_group 0;" ::: "memory");
}
__device__ __forceinline__ uint32_t pkh(hf a, hf b) {
    __half2 t = __halves2half2(a, b);
    return *(uint32_t*)&t;
}

// ---------------- fused weight conversion ------------------------------------
struct ConvDescs {
    const float* src[11];
    long         start4[11];
    size_t       dst[11];
    int          mode[11];
    int          off[11];
};

__global__ __launch_bounds__(256) void conv_all(ConvDescs D,
                                                hf* __restrict__ Ht,
                                                long total4) {
    long stride = (long)gridDim.x * blockDim.x;
    for (long i = (long)blockIdx.x * blockDim.x + threadIdx.x; i < total4; i += stride) {
        int seg = 0;
        #pragma unroll
        for (int j = 1; j < 11; j++) if (i >= D.start4[j]) seg = j;
        long local = i - D.start4[seg];
        float4 v = ((const float4*)D.src[seg])[local];
        size_t o;
        int mode = D.mode[seg];
        if (mode == 0) {
            o = D.dst[seg] + (size_t)local * 4;
        } else {
            long l    = local >> 18;
            long rem  = local & ((1L << 18) - 1);
            long k    = rem >> 8;
            long colc = (rem & 255) << 2;
            if (mode == 1)
                o = D.dst[seg] + (size_t)l * 3145728 + (size_t)k * 3072 + D.off[seg] + colc;
            else
                o = D.dst[seg] + (size_t)l * 2097152 + (size_t)k * 2048 + D.off[seg] + colc;
        }
        *(__half2*)(Ht + o)     = __floats2half2_rn(v.x, v.y);
        *(__half2*)(Ht + o + 2) = __floats2half2_rn(v.z, v.w);
    }
}

__global__ void bias_all(const float* __restrict__ q, const float* __restrict__ k,
                         const float* __restrict__ v, const float* __restrict__ ck,
                         const float* __restrict__ cv, float* __restrict__ d) {
    int i = blockIdx.x * blockDim.x + threadIdx.x;
    if (i < NLAYER * 3072) {
        int l = i / 3072, j = i - l * 3072;
        d[i] = (j < 1024) ? q[l*1024 + j]
             : (j < 2048) ? k[l*1024 + j - 1024]
                          : v[l*1024 + j - 2048];
    } else {
        int r = i - NLAYER * 3072;
        int l = r / 2048, j = r - l * 2048;
        d[i] = (j < 1024) ? ck[l*1024 + j] : cv[l*1024 + j - 1024];
    }
}

// ---------------- 128-row-tile GEMM (TERMS=2 or 1), 2x4 warp grid, 4 stages ---
template<int TERMS>
__device__ __forceinline__ void load_stage(uint32_t stb,
        const hf* __restrict__ Ahp, const hf* __restrict__ Alp, int lda,
        const hf* __restrict__ Bp, int ldb,
        int k0, int tid) {
    const uint32_t BOFF = (TERMS == 2) ? 16384u : 8192u;
    {
        int r0 = tid >> 2, c0 = tid & 3;
        const hf* a = Ahp + k0 + c0 * 8;
        #pragma unroll
        for (int h2 = 0; h2 < 2; h2++) {
            int row = r0 + h2 * 64;
            uint32_t d = stb + row * 64 + ((c0 ^ (row & 3)) << 4);
            cp16(d, a + (size_t)row * lda);
        }
        if (TERMS == 2) {
            const hf* a2 = Alp + k0 + c0 * 8;
            #pragma unroll
            for (int h2 = 0; h2 < 2; h2++) {
                int row = r0 + h2 * 64;
                uint32_t d = stb + 8192 + row * 64 + ((c0 ^ (row & 3)) << 4);
                cp16(d, a2 + (size_t)row * lda);
            }
        }
    }
    {
        int r0 = tid >> 4, c = tid & 15;
        const hf* b = Bp + c * 8;
        #pragma unroll
        for (int h2 = 0; h2 < 2; h2++) {
            int r = r0 + h2 * 16;
            uint32_t d = stb + BOFF + r * 256 + ((c ^ (r & 7)) << 4);
            cp16(d, b + (size_t)(k0 + r) * ldb);
        }
    }
    cp_commit();
}

template<int MODE, int TERMS>
__global__ __launch_bounds__(256)
void mma_gemm(const hf* __restrict__ Ah, const hf* __restrict__ Al,
              const hf* __restrict__ B,
              const float* __restrict__ bias,
              float* __restrict__ C, hf* __restrict__ Chi, hf* __restrict__ Clo,
              int M, int N, int K, int ldb, int ldc)
{
    extern __shared__ char smem[];
    const uint32_t SSZ  = (TERMS == 2) ? 24576u : 16384u;
    const uint32_t BOFF = (TERMS == 2) ? 16384u : 8192u;
    uint32_t sbase = (uint32_t)__cvta_generic_to_shared(smem);
    int tid = threadIdx.x, lane = tid & 31, wid = tid >> 5;
    int wm = wid & 1, wn = wid >> 1;           // 2 (M) x 4 (N) warp grid
    int bm = blockIdx.x * 128, bn = blockIdx.y * 128;

    const hf* pAh = Ah + (size_t)bm * K;
    const hf* pAl = Al + (size_t)bm * K;
    const hf* pB  = B + bn;

    float acc[4][4][4];
    #pragma unroll
    for (int a = 0; a < 4; a++)
        #pragma unroll
        for (int b2 = 0; b2 < 4; b2++)
            #pragma unroll
            for (int d = 0; d < 4; d++) acc[a][b2][d] = 0.f;

    const int NCH = K >> 5;
    load_stage<TERMS>(sbase,           pAh, pAl, K, pB, ldb, 0,  tid);
    load_stage<TERMS>(sbase + SSZ,     pAh, pAl, K, pB, ldb, 32, tid);
    load_stage<TERMS>(sbase + 2 * SSZ, pAh, pAl, K, pB, ldb, 64, tid);

    int a_r  = wm * 64 + (lane & 15);
    int a_ck = (lane >> 4) & 1;
    int b_rr = ((lane >> 3) & 1) * 8 + (lane & 7);
    int b_cc = wn * 4 + (lane >> 4);

    for (int c = 0; c < NCH; c++) {
        cp_waitg(NCH - c);
        __syncthreads();
        if (c + 3 < NCH)
            load_stage<TERMS>(sbase + ((c + 3) & 3) * SSZ, pAh, pAl, K, pB, ldb,
                              (c + 3) << 5, tid);

        uint32_t stb = sbase + (c & 3) * SSZ;
        #pragma unroll
        for (int k16 = 0; k16 < 2; k16++) {
            uint32_t a_hi[4][4], a_lo[4][4];
            #pragma unroll
            for (int mf = 0; mf < 4; mf++) {
                int row = a_r + mf * 16;
                int ck  = k16 * 2 + a_ck;
                uint32_t addr = stb + row * 64 + ((ck ^ (row & 3)) << 4);
                ldsm4(a_hi[mf], addr);
                if (TERMS == 2) ldsm4(a_lo[mf], addr + 8192);
            }
            int rr = k16 * 16 + b_rr;
            #pragma unroll
            for (int np2 = 0; np2 < 2; np2++) {
                int cc = b_cc + np2 * 2;
                uint32_t addr = stb + BOFF + rr * 256 + ((cc ^ (rr & 7)) << 4);
                uint32_t bv[4];
                ldsm4t(bv, addr);
                #pragma unroll
                for (int mf = 0; mf < 4; mf++) {
                    mma16816(acc[mf][np2*2],   a_hi[mf], bv);
                    mma16816(acc[mf][np2*2+1], a_hi[mf], bv + 2);
                    if (TERMS == 2) {
                        mma16816(acc[mf][np2*2],   a_lo[mf], bv);
                        mma16816(acc[mf][np2*2+1], a_lo[mf], bv + 2);
                    }
                }
            }
        }
    }

    __syncthreads();

    #pragma unroll
    for (int mf = 0; mf < 4; mf++) {
        int row0 = bm + wm * 64 + mf * 16 + (lane >> 2);
        #pragma unroll
        for (int nf = 0; nf < 4; nf++) {
            int col = bn + wn * 32 + nf * 8 + ((lane & 3) << 1);
            float bb0 = bias[col], bb1 = bias[col + 1];
            float v0 = acc[mf][nf][0] + bb0, v1 = acc[mf][nf][1] + bb1;
            float v2 = acc[mf][nf][2] + bb0, v3 = acc[mf][nf][3] + bb1;
            if (MODE == 2) {
                v0 = fmaxf(v0, 0.f); v1 = fmaxf(v1, 0.f);
                v2 = fmaxf(v2, 0.f); v3 = fmaxf(v3, 0.f);
            }
            if (MODE == 0) {
                float2 o0; o0.x = v0; o0.y = v1;
                float2 o1; o1.x = v2; o1.y = v3;
                *(float2*)(C + (size_t)row0 * ldc + col) = o0;
                *(float2*)(C + (size_t)(row0 + 8) * ldc + col) = o1;
            } else {
                hf h0 = __float2half_rn(v0), h1 = __float2half_rn(v1);
                hf h2 = __float2half_rn(v2), h3 = __float2half_rn(v3);
                *(__half2*)(Chi + (size_t)row0 * ldc + col)       = __halves2half2(h0, h1);
                *(__half2*)(Chi + (size_t)(row0 + 8) * ldc + col) = __halves2half2(h2, h3);
                *(__half2*)(Clo + (size_t)row0 * ldc + col) =
                    __floats2half2_rn(v0 - __half2float(h0), v1 - __half2float(h1));
                *(__half2*)(Clo + (size_t)(row0 + 8) * ldc + col) =
                    __floats2half2_rn(v2 - __half2float(h2), v3 - __half2float(h3));
            }
        }
    }
}

#define GEMM_SMEM2 (4*24576)
#define GEMM_SMEM1 (4*16384)

// ---------------- 64-row-tile GEMM, 4 stages ----------------------------------
#define GEMM_SMEM64 (4*16384)

__device__ __forceinline__ void load_stage64(uint32_t stb,
        const hf* __restrict__ Ahp, const hf* __restrict__ Alp, int lda,
        const hf* __restrict__ Bp, int ldb,
        int k0, int tid) {
    {
        int r0 = tid >> 2, c0 = tid & 3;
        uint32_t d = stb + r0 * 64 + ((c0 ^ (r0 & 3)) << 4);
        cp16(d,        Ahp + k0 + c0 * 8 + (size_t)r0 * lda);
        cp16(d + 4096, Alp + k0 + c0 * 8 + (size_t)r0 * lda);
    }
    {
        int r0 = tid >> 4, c = tid & 15;
        const hf* b = Bp + c * 8;
        #pragma unroll
        for (int h2 = 0; h2 < 2; h2++) {
            int r = r0 + h2 * 16;
            uint32_t d = stb + 8192 + r * 256 + ((c ^ (r & 7)) << 4);
            cp16(d, b + (size_t)(k0 + r) * ldb);
        }
    }
    cp_commit();
}

template<int MODE>
__global__ __launch_bounds__(256)
void mma_gemm64(const hf* __restrict__ Ah, const hf* __restrict__ Al,
                const hf* __restrict__ B,
                const float* __restrict__ bias,
                float* __restrict__ C, hf* __restrict__ Chi, hf* __restrict__ Clo,
                int M, int N, int K, int ldb, int ldc)
{
    extern __shared__ char smem[];
    const uint32_t SSZ = 16384u, BOFF = 8192u;
    uint32_t sbase = (uint32_t)__cvta_generic_to_shared(smem);
    int tid = threadIdx.x, lane = tid & 31, wid = tid >> 5;
    int wm = wid & 1, wn = wid >> 1;
    int bm = blockIdx.x * 64, bn = blockIdx.y * 128;

    const hf* pAh = Ah + (size_t)bm * K;
    const hf* pAl = Al + (size_t)bm * K;
    const hf* pB  = B + bn;

    float acc[2][4][4];
    #pragma unroll
    for (int a = 0; a < 2; a++)
        #pragma unroll
        for (int b2 = 0; b2 < 4; b2++)
            #pragma unroll
            for (int d = 0; d < 4; d++) acc[a][b2][d] = 0.f;

    const int NCH = K >> 5;
    load_stage64(sbase,           pAh, pAl, K, pB, ldb, 0,  tid);
    load_stage64(sbase + SSZ,     pAh, pAl, K, pB, ldb, 32, tid);
    load_stage64(sbase + 2 * SSZ, pAh, pAl, K, pB, ldb, 64, tid);

    int a_r  = wm * 32 + (lane & 15);
    int a_ck = (lane >> 4) & 1;
    int b_rr = ((lane >> 3) & 1) * 8 + (lane & 7);
    int b_cc = wn * 4 + (lane >> 4);

    for (int c = 0; c < NCH; c++) {
        cp_waitg(NCH - c);
        __syncthreads();
        if (c + 3 < NCH)
            load_stage64(sbase + ((c + 3) & 3) * SSZ, pAh, pAl, K, pB, ldb,
                         (c + 3) << 5, tid);

        uint32_t stb = sbase + (c & 3) * SSZ;
        #pragma unroll
        for (int k16 = 0; k16 < 2; k16++) {
            uint32_t a_hi[2][4], a_lo[2][4];
            #pragma unroll
            for (int mf = 0; mf < 2; mf++) {
                int row = a_r + mf * 16;
                int ck  = k16 * 2 + a_ck;
                uint32_t addr = stb + row * 64 + ((ck ^ (row & 3)) << 4);
                ldsm4(a_hi[mf], addr);
                ldsm4(a_lo[mf], addr + 4096);
            }
            int rr = k16 * 16 + b_rr;
            #pragma unroll
            for (int np2 = 0; np2 < 2; np2++) {
                int cc = b_cc + np2 * 2;
                uint32_t addr = stb + BOFF + rr * 256 + ((cc ^ (rr & 7)) << 4);
                uint32_t bv[4];
                ldsm4t(bv, addr);
                #pragma unroll
                for (int mf = 0; mf < 2; mf++) {
                    mma16816(acc[mf][np2*2],   a_hi[mf], bv);
                    mma16816(acc[mf][np2*2+1], a_hi[mf], bv + 2);
                    mma16816(acc[mf][np2*2],   a_lo[mf], bv);
                    mma16816(acc[mf][np2*2+1], a_lo[mf], bv + 2);
                }
            }
        }
    }

    __syncthreads();

    #pragma unroll
    for (int mf = 0; mf < 2; mf++) {
        int row0 = bm + wm * 32 + mf * 16 + (lane >> 2);
        #pragma unroll
        for (int nf = 0; nf < 4; nf++) {
            int col = bn + wn * 32 + nf * 8 + ((lane & 3) << 1);
            float bb0 = bias[col], bb1 = bias[col + 1];
            float v0 = acc[mf][nf][0] + bb0, v1 = acc[mf][nf][1] + bb1;
            float v2 = acc[mf][nf][2] + bb0, v3 = acc[mf][nf][3] + bb1;
            if (MODE == 0) {
                float2 o0; o0.x = v0; o0.y = v1;
                float2 o1; o1.x = v2; o1.y = v3;
                *(float2*)(C + (size_t)row0 * ldc + col) = o0;
                *(float2*)(C + (size_t)(row0 + 8) * ldc + col) = o1;
            } else {
                hf h0 = __float2half_rn(v0), h1 = __float2half_rn(v1);
                hf h2 = __float2half_rn(v2), h3 = __float2half_rn(v3);
                *(__half2*)(Chi + (size_t)row0 * ldc + col)       = __halves2half2(h0, h1);
                *(__half2*)(Chi + (size_t)(row0 + 8) * ldc + col) = __halves2half2(h2, h3);
                *(__half2*)(Clo + (size_t)row0 * ldc + col) =
                    __floats2half2_rn(v0 - __half2float(h0), v1 - __half2float(h1));
                *(__half2*)(Clo + (size_t)(row0 + 8) * ldc + col) =
                    __floats2half2_rn(v2 - __half2float(h2), v3 - __half2float(h3));
            }
        }
    }
}

// ---------------- flash attention (fp16 single-term Q and P) ------------------
// smem: Q@0 16KB | K@16384 8KB | V@24576 8KB
#define FLASH_SMEM 32768

template<bool CAUSAL>
__global__ __launch_bounds__(256)
void flash_attn(const hf* __restrict__ Qh, int ldq, int qoff,
                const hf* __restrict__ Ks, int ldk, int koff,
                const hf* __restrict__ Vs, int ldv, int voff,
                const int* __restrict__ tgt,
                hf* __restrict__ Oh, hf* __restrict__ Ol, int ldo,
                int Sq, int Sk)
{
    extern __shared__ char sm[];
    uint32_t sb = (uint32_t)__cvta_generic_to_shared(sm);
    int tid = threadIdx.x, lane = tid & 31, w = tid >> 5;
    int bh = blockIdx.y, b = bh >> 4, h = bh & 15;
    int q0 = (CAUSAL ? (gridDim.x - 1 - blockIdx.x) : blockIdx.x) * 128;

    {
        const hf* qh = Qh + (size_t)(b * Sq + q0) * ldq + qoff + h * 64;
        #pragma unroll
        for (int i = 0; i < 4; i++) {
            int idx = tid + i * 256;
            int row = idx >> 3, c = idx & 7;
            uint32_t off = row * 128 + ((c ^ (row & 7)) << 4);
            *(uint4*)(sm + off) = *(const uint4*)(qh + (size_t)row * ldq + c * 8);
        }
    }

    int rq = lane >> 2;
    int qrow0 = q0 + w * 16 + rq;
    int qrow1 = qrow0 + 8;
    bool pad0 = false, pad1 = false;
    if (CAUSAL) {
        pad0 = (tgt[b * Sq + qrow0] == 0);
        pad1 = (tgt[b * Sq + qrow1] == 0);
    }

    float O[8][4];
    #pragma unroll
    for (int i = 0; i < 8; i++)
        #pragma unroll
        for (int j = 0; j < 4; j++) O[i][j] = 0.f;
    float m0 = -1e30f, m1 = -1e30f, s0 = 0.f, s1 = 0.f;

    int kend = CAUSAL ? (q0 + 128) : Sk;

    for (int k0 = 0; k0 < kend; k0 += 64) {
        __syncthreads();
        {
            const hf* srcs[2] = {
                Ks + (size_t)(b * Sk + k0) * ldk + koff + h * 64,
                Vs + (size_t)(b * Sk + k0) * ldv + voff + h * 64 };
            int lds[2] = { ldk, ldv };
            uint32_t dsts[2] = { 16384u, 24576u };
            #pragma unroll
            for (int t = 0; t < 2; t++) {
                #pragma unroll
                for (int i = 0; i < 2; i++) {
                    int idx = tid + i * 256;
                    int row = idx >> 3, c = idx & 7;
                    *(uint4*)(sm + dsts[t] + row * 128 + ((c ^ (row & 7)) << 4)) =
                        *(const uint4*)(srcs[t] + (size_t)row * lds[t] + c * 8);
                }
            }
        }
        __syncthreads();

        float S[8][4];
        #pragma unroll
        for (int i = 0; i < 8; i++)
            #pragma unroll
            for (int j = 0; j < 4; j++) S[i][j] = 0.f;

        #pragma unroll
        for (int ks = 0; ks < 4; ks++) {
            int arow = w * 16 + (lane & 15);
            int ac = ks * 2 + ((lane >> 4) & 1);
            uint32_t qa = sb + arow * 128 + ((ac ^ (arow & 7)) << 4);
            uint32_t ah[4];
            ldsm4(ah, qa);
            #pragma unroll
            for (int np = 0; np < 4; np++) {
                int brow = np * 16 + (lane & 7) + ((lane >> 4) & 1) * 8;
                int bc = ks * 2 + ((lane >> 3) & 1);
                uint32_t ka = sb + 16384 + brow * 128 + ((bc ^ (brow & 7)) << 4);
                uint32_t kb[4];
                ldsm4(kb, ka);
                mma16816(S[np*2],   ah, kb);     mma16816(S[np*2+1],   ah, kb + 2);
            }
        }

        #pragma unroll
        for (int nt = 0; nt < 8; nt++) {
            int col = k0 + nt * 8 + 2 * (lane & 3);
            #pragma unroll
            for (int e = 0; e < 4; e++) S[nt][e] *= 0.125f;
            if (CAUSAL && k0 >= q0) {
                if (col     > qrow0) S[nt][0] = -1e9f;
                if (col + 1 > qrow0) S[nt][1] = -1e9f;
                if (col     > qrow1) S[nt][2] = -1e9f;
                if (col + 1 > qrow1) S[nt][3] = -1e9f;
            }
            if (CAUSAL) {
                if (pad0) { S[nt][0] = -1e9f; S[nt][1] = -1e9f; }
                if (pad1) { S[nt][2] = -1e9f; S[nt][3] = -1e9f; }
            }
        }

        float mx0 = -1e30f, mx1 = -1e30f;
        #pragma unroll
        for (int nt = 0; nt < 8; nt++) {
            mx0 = fmaxf(mx0, fmaxf(S[nt][0], S[nt][1]));
            mx1 = fmaxf(mx1, fmaxf(S[nt][2], S[nt][3]));
        }
        mx0 = fmaxf(mx0, __shfl_xor_sync(0xffffffffu, mx0, 1));
        mx0 = fmaxf(mx0, __shfl_xor_sync(0xffffffffu, mx0, 2));
        mx1 = fmaxf(mx1, __shfl_xor_sync(0xffffffffu, mx1, 1));
        mx1 = fmaxf(mx1, __shfl_xor_sync(0xffffffffu, mx1, 2));
        float mn0 = fmaxf(m0, mx0), mn1 = fmaxf(m1, mx1);
        float al0 = __expf(m0 - mn0), al1 = __expf(m1 - mn1);
        m0 = mn0; m1 = mn1;
        float ps0 = 0.f, ps1 = 0.f;
        #pragma unroll
        for (int nt = 0; nt < 8; nt++) {
            S[nt][0] = __expf(S[nt][0] - mn0);
            S[nt][1] = __expf(S[nt][1] - mn0);
            S[nt][2] = __expf(S[nt][2] - mn1);
            S[nt][3] = __expf(S[nt][3] - mn1);
            ps0 += S[nt][0] + S[nt][1];
            ps1 += S[nt][2] + S[nt][3];
        }
        ps0 += __shfl_xor_sync(0xffffffffu, ps0, 1);
        ps0 += __shfl_xor_sync(0xffffffffu, ps0, 2);
        ps1 += __shfl_xor_sync(0xffffffffu, ps1, 1);
        ps1 += __shfl_xor_sync(0xffffffffu, ps1, 2);
        s0 = s0 * al0 + ps0;
        s1 = s1 * al1 + ps1;
        #pragma unroll
        for (int nt = 0; nt < 8; nt++) {
            O[nt][0] *= al0; O[nt][1] *= al0;
            O[nt][2] *= al1; O[nt][3] *= al1;
        }

        #pragma unroll
        for (int ks = 0; ks < 4; ks++) {
            uint32_t pah[4];
            #pragma unroll
            for (int half = 0; half < 2; half++) {
                pah[half*2 + 0] = pkh(__float2half_rn(S[2*ks+half][0]),
                                      __float2half_rn(S[2*ks+half][1]));
                pah[half*2 + 1] = pkh(__float2half_rn(S[2*ks+half][2]),
                                      __float2half_rn(S[2*ks+half][3]));
            }
            #pragma unroll
            for (int np = 0; np < 4; np++) {
                int rr = ks * 16 + ((lane >> 3) & 1) * 8 + (lane & 7);
                int cc = np * 2 + (lane >> 4);
                uint32_t va = sb + 24576 + rr * 128 + ((cc ^ (rr & 7)) << 4);
                uint32_t vb[4];
                ldsm4t(vb, va);
                mma16816(O[np*2],   pah, vb);     mma16816(O[np*2+1],   pah, vb + 2);
            }
        }
    }

    float inv0 = 1.f / s0, inv1 = 1.f / s1;
    size_t tr0 = (size_t)(b * Sq + qrow0) * ldo;
    size_t tr1 = (size_t)(b * Sq + qrow1) * ldo;
    #pragma unroll
    for (int nt = 0; nt < 8; nt++) {
        int col = h * 64 + nt * 8 + 2 * (lane & 3);
        float v0 = O[nt][0] * inv0, v1 = O[nt][1] * inv0;
        float v2 = O[nt][2] * inv1, v3 = O[nt][3] * inv1;
        hf h0 = __float2half_rn(v0), h1 = __float2half_rn(v1);
        hf h2 = __float2half_rn(v2), h3 = __float2half_rn(v3);
        *(__half2*)(Oh + tr0 + col) = __halves2half2(h0, h1);
        *(__half2*)(Oh + tr1 + col) = __halves2half2(h2, h3);
        *(__half2*)(Ol + tr0 + col) =
            __floats2half2_rn(v0 - __half2float(h0), v1 - __half2float(h1));
        *(__half2*)(Ol + tr1 + col) =
            __floats2half2_rn(v2 - __half2float(h2), v3 - __half2float(h3));
    }
}

// ---------------- positional encoding / embed --------------------------------
__device__ __forceinline__ float pe_val(int s, int d) {
    const float c = -0.0089944730195079f;
    int i2 = d & ~1;
    float freq = expf((float)i2 * c);
    float ang  = (float)s * freq;
    return (d & 1) ? cosf(ang) : sinf(ang);
}

__global__ void embed_pe(const int* __restrict__ tgt, const float* __restrict__ emb,
                         float* __restrict__ X, hf* __restrict__ Xh, hf* __restrict__ Xl) {
    int row = blockIdx.x;
    int s   = row % TGT;
    int tok = tgt[row];
    int t   = threadIdx.x;
    #pragma unroll
    for (int i = 0; i < 4; i++) {
        int d = t * 4 + i;
        float v = emb[(size_t)tok * D_MODEL + d] + pe_val(s, d);
        X[(size_t)row * D_MODEL + d] = v;
        hf h = __float2half_rn(v);
        Xh[(size_t)row * D_MODEL + d] = h;
        Xl[(size_t)row * D_MODEL + d] = __float2half_rn(v - __half2float(h));
    }
}

__global__ void src_pe(const float* __restrict__ src,
                       hf* __restrict__ Eh, hf* __restrict__ El) {
    int row = blockIdx.x;
    int s   = row % SRCL;
    int t   = threadIdx.x;
    #pragma unroll
    for (int i = 0; i < 4; i++) {
        int d = t * 4 + i;
        float v = src[(size_t)row * D_MODEL + d] + pe_val(s, d);
        hf h = __float2half_rn(v);
        Eh[(size_t)row * D_MODEL + d] = h;
        El[(size_t)row * D_MODEL + d] = __float2half_rn(v - __half2float(h));
    }
}

// ---------------- add + LayerNorm --------------------------------------------
__global__ __launch_bounds__(256) void add_ln(
    const float* __restrict__ X, const float* __restrict__ A,
    const float* __restrict__ G, const float* __restrict__ Bt,
    float* __restrict__ Y, hf* __restrict__ Yh, hf* __restrict__ Yl)
{
    __shared__ float red[8];
    __shared__ float bcast;
    int row = blockIdx.x;
    int t = threadIdx.x;
    int lane = t & 31, wid = t >> 5;

    float4 xv = *(const float4*)(X + (size_t)row * D_MODEL + t * 4);
    float4 av = *(const float4*)(A + (size_t)row * D_MODEL + t * 4);
    float v0 = xv.x + av.x, v1 = xv.y + av.y, v2 = xv.z + av.z, v3 = xv.w + av.w;

    float s = v0 + v1 + v2 + v3;
    #pragma unroll
    for (int o = 16; o; o >>= 1) s += __shfl_xor_sync(0xffffffffu, s, o);
    if (lane == 0) red[wid] = s;
    __syncthreads();
    if (t == 0) {
        float tot = 0.f;
        #pragma unroll
        for (int i = 0; i < 8; i++) tot += red[i];
        bcast = tot;
    }
    __syncthreads();
    float mean = bcast * (1.f / 1024.f);

    float d0 = v0 - mean, d1 = v1 - mean, d2 = v2 - mean, d3 = v3 - mean;
    s = d0 * d0 + d1 * d1 + d2 * d2 + d3 * d3;
    #pragma unroll
    for (int o = 16; o; o >>= 1) s += __shfl_xor_sync(0xffffffffu, s, o);
    if (lane == 0) red[wid] = s;
    __syncthreads();
    if (t == 0) {
        float tot = 0.f;
        #pragma unroll
        for (int i = 0; i < 8; i++) tot += red[i];
        bcast = tot;
    }
    __syncthreads();
    float rstd = rsqrtf(bcast * (1.f / 1024.f) + 1e-5f);

    int c = t * 4;
    float o0 = d0 * rstd * G[c + 0] + Bt[c + 0];
    float o1 = d1 * rstd * G[c + 1] + Bt[c + 1];
    float o2 = d2 * rstd * G[c + 2] + Bt[c + 2];
    float o3 = d3 * rstd * G[c + 3] + Bt[c + 3];
    float4 o; o.x = o0; o.y = o1; o.z = o2; o.w = o3;
    *(float4*)(Y + (size_t)row * D_MODEL + c) = o;
    hf h0 = __float2half_rn(o0), h1 = __float2half_rn(o1);
    hf h2 = __float2half_rn(o2), h3 = __float2half_rn(o3);
    *(__half2*)(Yh + (size_t)row * D_MODEL + c)     = __halves2half2(h0, h1);
    *(__half2*)(Yh + (size_t)row * D_MODEL + c + 2) = __halves2half2(h2, h3);
    *(__half2*)(Yl + (size_t)row * D_MODEL + c) =
        __floats2half2_rn(o0 - __half2float(h0), o1 - __half2float(h1));
    *(__half2*)(Yl + (size_t)row * D_MODEL + c + 2) =
        __floats2half2_rn(o2 - __half2float(h2), o3 - __half2float(h3));
}

// ---------------- host pointers ----------------------------------------------
static hf *h_xhi, *h_xlo, *h_ehi, *h_elo, *h_qkvh, *h_qkvl, *h_kvh, *h_kvl;
static hf *h_ahi, *h_alo, *h_w;
static float *h_x, *h_tmp, *h_bias;

// ---------------- orchestration ----------------------------------------------
extern "C" void kernel_launch(void* const* d_in, const int* in_sizes, int n_in,
                              void* d_out, int out_size) {
    bool layoutA = (in_sizes[3] == 8 * 1024 * 1024);

    const float* src = (const float*)d_in[0];
    const int*   tgt = (const int*)  d_in[1];
    const float* emb = (const float*)d_in[2];

    const float *sa_wq, *sa_bq, *sa_wk, *sa_bk, *sa_wv, *sa_bv, *sa_wo, *sa_bo;
    const float *ca_wq, *ca_bq, *ca_wk, *ca_bk, *ca_wv, *ca_bv, *ca_wo, *ca_bo;
    const float *w1, *b1, *w2, *b2;
    const float *n1g, *n1b, *n2g, *n2b, *n3g, *n3b;
    const float *fc_w, *fc_b;

    if (layoutA) {
        sa_wq = (const float*)d_in[3];  sa_bq = (const float*)d_in[4];
        sa_wk = (const float*)d_in[5];  sa_bk = (const float*)d_in[6];
        sa_wv = (const float*)d_in[7];  sa_bv = (const float*)d_in[8];
        sa_wo = (const float*)d_in[9];  sa_bo = (const float*)d_in[10];
        ca_wq = (const float*)d_in[11]; ca_bq = (const float*)d_in[12];
        ca_wk = (const float*)d_in[13]; ca_bk = (const float*)d_in[14];
        ca_wv = (const float*)d_in[15]; ca_bv = (const float*)d_in[16];
        ca_wo = (const float*)d_in[17]; ca_bo = (const float*)d_in[18];
        w1 = (const float*)d_in[19]; b1 = (const float*)d_in[20];
        w2 = (const float*)d_in[21]; b2 = (const float*)d_in[22];
        n1g = (const float*)d_in[23]; n1b = (const float*)d_in[24];
        n2g = (const float*)d_in[25]; n2b = (const float*)d_in[26];
        n3g = (const float*)d_in[27]; n3b = (const float*)d_in[28];
        fc_w = (const float*)d_in[29]; fc_b = (const float*)d_in[30];
    } else {
        fc_w = (const float*)d_in[3];  fc_b = (const float*)d_in[4];
        sa_wq = (const float*)d_in[5];  sa_bq = (const float*)d_in[6];
        sa_wk = (const float*)d_in[7];  sa_bk = (const float*)d_in[8];
        sa_wv = (const float*)d_in[9];  sa_bv = (const float*)d_in[10];
        sa_wo = (const float*)d_in[11]; sa_bo = (const float*)d_in[12];
        ca_wq = (const float*)d_in[13]; ca_bq = (const float*)d_in[14];
        ca_wk = (const float*)d_in[15]; ca_bk = (const float*)d_in[16];
        ca_wv = (const float*)d_in[17]; ca_bv = (const float*)d_in[18];
        ca_wo = (const float*)d_in[19]; ca_bo = (const float*)d_in[20];
        w1 = (const float*)d_in[21]; b1 = (const float*)d_in[22];
        w2 = (const float*)d_in[23]; b2 = (const float*)d_in[24];
        n1g = (const float*)d_in[25]; n2g = (const float*)d_in[26];
        n3g = (const float*)d_in[27]; n1b = (const float*)d_in[28];
        n2b = (const float*)d_in[29]; n3b = (const float*)d_in[30];
    }

    cudaGetSymbolAddress((void**)&h_x,    g_x);
    cudaGetSymbolAddress((void**)&h_tmp,  g_tmp);
    cudaGetSymbolAddress((void**)&h_xhi,  g_xhi);
    cudaGetSymbolAddress((void**)&h_xlo,  g_xlo);
    cudaGetSymbolAddress((void**)&h_ehi,  g_ehi);
    cudaGetSymbolAddress((void**)&h_elo,  g_elo);
    cudaGetSymbolAddress((void**)&h_qkvh, g_qkvh);
    cudaGetSymbolAddress((void**)&h_qkvl, g_qkvl);
    cudaGetSymbolAddress((void**)&h_kvh,  g_kvh);
    cudaGetSymbolAddress((void**)&h_kvl,  g_kvl);
    cudaGetSymbolAddress((void**)&h_ahi,  g_ahi);
    cudaGetSymbolAddress((void**)&h_alo,  g_alo);
    cudaGetSymbolAddress((void**)&h_w,    g_w);
    cudaGetSymbolAddress((void**)&h_bias, g_biasall);

    cudaFuncSetAttribute((const void*)mma_gemm<0,2>, cudaFuncAttributeMaxDynamicSharedMemorySize, GEMM_SMEM2);
    cudaFuncSetAttribute((const void*)mma_gemm<1,2>, cudaFuncAttributeMaxDynamicSharedMemorySize, GEMM_SMEM2);
    cudaFuncSetAttribute((const void*)mma_gemm<2,2>, cudaFuncAttributeMaxDynamicSharedMemorySize, GEMM_SMEM2);
    cudaFuncSetAttribute((const void*)mma_gemm<0,1>, cudaFuncAttributeMaxDynamicSharedMemorySize, GEMM_SMEM1);
    cudaFuncSetAttribute((const void*)mma_gemm64<0>, cudaFuncAttributeMaxDynamicSharedMemorySize, GEMM_SMEM64);
    cudaFuncSetAttribute((const void*)mma_gemm64<1>, cudaFuncAttributeMaxDynamicSharedMemorySize, GEMM_SMEM64);
    cudaFuncSetAttribute((const void*)flash_attn<true>,  cudaFuncAttributeMaxDynamicSharedMemorySize, FLASH_SMEM);
    cudaFuncSetAttribute((const void*)flash_attn<false>, cudaFuncAttributeMaxDynamicSharedMemorySize, FLASH_SMEM);

    const int Mx = NB * TGT;    // 2048
    const int Me = NB * SRCL;   // 1024

    {
        ConvDescs D;
        const long C2 = 2097152, C8 = 8388608;
        const float* srcs[11] = { sa_wq, sa_wk, sa_wv, sa_wo, ca_wq,
                                  ca_wk, ca_wv, ca_wo, w1, w2, fc_w };
        long starts[11] = { 0, C2, 2*C2, 3*C2, 4*C2, 5*C2, 6*C2, 7*C2,
                            8*C2, 8*C2 + C8, 8*C2 + 2*C8 };
        size_t dsts[11] = { OFF_QKV, OFF_QKV, OFF_QKV, OFF_SAO, OFF_CAQ,
                            OFF_CAKV, OFF_CAKV, OFF_CAO, OFF_FF1, OFF_FF2, OFF_FC };
        int modes[11] = { 1, 1, 1, 0, 0, 2, 2, 0, 0, 0, 0 };
        int offs[11]  = { 0, 1024, 2048, 0, 0, 0, 1024, 0, 0, 0, 0 };
        for (int i = 0; i < 11; i++) {
            D.src[i] = srcs[i]; D.start4[i] = starts[i];
            D.dst[i] = dsts[i]; D.mode[i] = modes[i]; D.off[i] = offs[i];
        }
        long total4 = 8*C2 + 2*C8 + 8192000;
        conv_all<<<4096, 256>>>(D, h_w, total4);
    }
    bias_all<<<160, 256>>>(sa_bq, sa_bk, sa_bv, ca_bk, ca_bv, h_bias);
    embed_pe<<<Mx, 256>>>(tgt, emb, h_x, h_xhi, h_xlo);

    bool did_src = false;

    for (int l = 0; l < NLAYER; l++) {
        const hf* Wqkv = h_w + OFF_QKV  + (size_t)l * 3145728;
        const hf* Wsao = h_w + OFF_SAO  + (size_t)l * 1048576;
        const hf* Wcaq = h_w + OFF_CAQ  + (size_t)l * 1048576;
        const hf* Wkv  = h_w + OFF_CAKV + (size_t)l * 2097152;
        const hf* Wcao = h_w + OFF_CAO  + (size_t)l * 1048576;
        const hf* Wf1  = h_w + OFF_FF1  + (size_t)l * 4194304;
        const hf* Wf2  = h_w + OFF_FF2  + (size_t)l * 4194304;

        // ---- self-attention ----
        mma_gemm<1,2><<<dim3(16, 24), 256, GEMM_SMEM2>>>(h_xhi, h_xlo, Wqkv,
            h_bias + (size_t)l * 3072, (float*)0, h_qkvh, h_qkvl, Mx, 3072, D_MODEL, 3072, 3072);
        if (!did_src) { src_pe<<<Me, 256>>>(src, h_ehi, h_elo); did_src = true; }
        flash_attn<true><<<dim3(4, 64), 256, FLASH_SMEM>>>(
            h_qkvh, 3072, 0, h_qkvh, 3072, 1024,
            h_qkvh, 3072, 2048, tgt, h_ahi, h_alo, 1024, TGT, TGT);
        mma_gemm64<0><<<dim3(32, 8), 256, GEMM_SMEM64>>>(h_ahi, h_alo, Wsao,
            sa_bo + l*D_MODEL, h_tmp, (hf*)0, (hf*)0, Mx, D_MODEL, D_MODEL, D_MODEL, D_MODEL);
        add_ln<<<Mx, 256>>>(h_x, h_tmp, n1g + l*D_MODEL, n1b + l*D_MODEL, h_x, h_xhi, h_xlo);

        // ---- cross-attention ----
        mma_gemm64<1><<<dim3(32, 8), 256, GEMM_SMEM64>>>(h_xhi, h_xlo, Wcaq,
            ca_bq + l*D_MODEL, (float*)0, h_qkvh, h_qkvl, Mx, D_MODEL, D_MODEL, D_MODEL, D_MODEL);
        mma_gemm64<1><<<dim3(16, 16), 256, GEMM_SMEM64>>>(h_ehi, h_elo, Wkv,
            h_bias + NLAYER*3072 + (size_t)l * 2048, (float*)0, h_kvh, h_kvl, Me, 2048, D_MODEL, 2048, 2048);
        flash_attn<false><<<dim3(4, 64), 256, FLASH_SMEM>>>(
            h_qkvh, 1024, 0, h_kvh, 2048, 0,
            h_kvh, 2048, 1024, (const int*)0, h_ahi, h_alo, 1024, TGT, SRCL);
        mma_gemm64<0><<<dim3(32, 8), 256, GEMM_SMEM64>>>(h_ahi, h_alo, Wcao,
            ca_bo + l*D_MODEL, h_tmp, (hf*)0, (hf*)0, Mx, D_MODEL, D_MODEL, D_MODEL, D_MODEL);
        add_ln<<<Mx, 256>>>(h_x, h_tmp, n2g + l*D_MODEL, n2b + l*D_MODEL, h_x, h_xhi, h_xlo);

        // ---- FFN ----
        mma_gemm<2,2><<<dim3(16, 32), 256, GEMM_SMEM2>>>(h_xhi, h_xlo, Wf1,
            b1 + (size_t)l*FFDIM, (float*)0, h_ahi, h_alo, Mx, FFDIM, D_MODEL, FFDIM, FFDIM);
        mma_gemm64<0><<<dim3(32, 8), 256, GEMM_SMEM64>>>(h_ahi, h_alo, Wf2,
            b2 + (size_t)l*D_MODEL, h_tmp, (hf*)0, (hf*)0, Mx, D_MODEL, FFDIM, D_MODEL, D_MODEL);
        add_ln<<<Mx, 256>>>(h_x, h_tmp, n3g + l*D_MODEL, n3b + l*D_MODEL, h_x, h_xhi, h_xlo);
    }

    // ---- final projection to vocab: single-term fp16 ----
    mma_gemm<0,1><<<dim3(16, 250), 256, GEMM_SMEM1>>>(h_xhi, h_xhi, h_w + OFF_FC,
        fc_b, (float*)d_out, (hf*)0, (hf*)0, Mx, VOCAB, D_MODEL, VOCAB, VOCAB);
    (void)n_in; (void)out_size;
}

// round 17
// speedup vs baseline: 1.2470x; 1.1591x over previous
#include <cuda_runtime.h>
#include <cuda_fp16.h>
#include <math.h>
#include <stdint.h>

#define D_MODEL 1024
#define NH      16
#define DK      64
#define NB      4
#define TGT     512
#define SRCL    256
#define NLAYER  8
#define FFDIM   4096
#define VOCAB   32000

typedef __half hf;

// ---------------- weight arena layout (elems) ---------------------------------
#define OFF_QKV  ((size_t)0)
#define OFF_SAO  ((size_t)25165824)
#define OFF_CAQ  ((size_t)33554432)
#define OFF_CAKV ((size_t)41943040)
#define OFF_CAO  ((size_t)58720256)
#define OFF_FF1  ((size_t)67108864)
#define OFF_FF2  ((size_t)100663296)
#define OFF_FC   ((size_t)134217728)
#define W_ELEMS  ((size_t)166985728)

// ---------------- scratch ----------------------------------------------------
__device__ float g_x   [NB*TGT*D_MODEL];
__device__ float g_tmp [NB*TGT*D_MODEL];
__device__ hf    g_xhi [NB*TGT*D_MODEL];
__device__ hf    g_xlo [NB*TGT*D_MODEL];
__device__ hf    g_ehi [NB*SRCL*D_MODEL];
__device__ hf    g_elo [NB*SRCL*D_MODEL];
__device__ hf    g_qkvh[NB*TGT*3*D_MODEL];
__device__ hf    g_kvh [NB*SRCL*2*D_MODEL];
__device__ hf    g_ahi [NB*TGT*FFDIM];
__device__ hf    g_w   [W_ELEMS];
__device__ float g_biasall[NLAYER*3072 + NLAYER*2048];

// ---------------- warp-MMA primitives ----------------------------------------
__device__ __forceinline__ void ldsm4(uint32_t* r, uint32_t addr) {
    asm volatile("ldmatrix.sync.aligned.m8n8.x4.shared.b16 {%0,%1,%2,%3}, [%4];"
                 : "=r"(r[0]), "=r"(r[1]), "=r"(r[2]), "=r"(r[3]) : "r"(addr));
}
__device__ __forceinline__ void ldsm4t(uint32_t* r, uint32_t addr) {
    asm volatile("ldmatrix.sync.aligned.m8n8.x4.trans.shared.b16 {%0,%1,%2,%3}, [%4];"
                 : "=r"(r[0]), "=r"(r[1]), "=r"(r[2]), "=r"(r[3]) : "r"(addr));
}
__device__ __forceinline__ void mma16816(float* d, const uint32_t* a, const uint32_t* b) {
    asm volatile("mma.sync.aligned.m16n8k16.row.col.f32.f16.f16.f32 "
                 "{%0,%1,%2,%3}, {%4,%5,%6,%7}, {%8,%9}, {%0,%1,%2,%3};"
                 : "+f"(d[0]), "+f"(d[1]), "+f"(d[2]), "+f"(d[3])
                 : "r"(a[0]), "r"(a[1]), "r"(a[2]), "r"(a[3]), "r"(b[0]), "r"(b[1]));
}
__device__ __forceinline__ void cp16(uint32_t dst, const void* src) {
    asm volatile("cp.async.cg.shared.global [%0], [%1], 16;" :: "r"(dst), "l"(src) : "memory");
}
__device__ __forceinline__ void cp_commit() {
    asm volatile("cp.async.commit_group;" ::: "memory");
}
__device__ __forceinline__ void cp_waitg(int tail_rem) {
    if (tail_rem >= 3)      asm volatile("cp.async.wait_group 2;" ::: "memory");
    else if (tail_rem == 2) asm volatile("cp.async.wait_group 1;" ::: "memory");
    else                    asm volatile("cp.async.wait_group 0;" ::: "memory");
}
__device__ __forceinline__ uint32_t pkh(hf a, hf b) {
    __half2 t = __halves2half2(a, b);
    return *(uint32_t*)&t;
}

// ---------------- fused weight conversion ------------------------------------
struct ConvDescs {
    const float* src[11];
    long         start4[11];
    size_t       dst[11];
    int          mode[11];
    int          off[11];
};

__global__ __launch_bounds__(256) void conv_all(ConvDescs D,
                                                hf* __restrict__ Ht,
                                                long total4) {
    long stride = (long)gridDim.x * blockDim.x;
    for (long i = (long)blockIdx.x * blockDim.x + threadIdx.x; i < total4; i += stride) {
        int seg = 0;
        #pragma unroll
        for (int j = 1; j < 11; j++) if (i >= D.start4[j]) seg = j;
        long local = i - D.start4[seg];
        float4 v = ((const float4*)D.src[seg])[local];
        size_t o;
        int mode = D.mode[seg];
        if (mode == 0) {
            o = D.dst[seg] + (size_t)local * 4;
        } else {
            long l    = local >> 18;
            long rem  = local & ((1L << 18) - 1);
            long k    = rem >> 8;
            long colc = (rem & 255) << 2;
            if (mode == 1)
                o = D.dst[seg] + (size_t)l * 3145728 + (size_t)k * 3072 + D.off[seg] + colc;
            else
                o = D.dst[seg] + (size_t)l * 2097152 + (size_t)k * 2048 + D.off[seg] + colc;
        }
        *(__half2*)(Ht + o)     = __floats2half2_rn(v.x, v.y);
        *(__half2*)(Ht + o + 2) = __floats2half2_rn(v.z, v.w);
    }
}

__global__ void bias_all(const float* __restrict__ q, const float* __restrict__ k,
                         const float* __restrict__ v, const float* __restrict__ ck,
                         const float* __restrict__ cv, float* __restrict__ d) {
    int i = blockIdx.x * blockDim.x + threadIdx.x;
    if (i < NLAYER * 3072) {
        int l = i / 3072, j = i - l * 3072;
        d[i] = (j < 1024) ? q[l*1024 + j]
             : (j < 2048) ? k[l*1024 + j - 1024]
                          : v[l*1024 + j - 2048];
    } else {
        int r = i - NLAYER * 3072;
        int l = r / 2048, j = r - l * 2048;
        d[i] = (j < 1024) ? ck[l*1024 + j] : cv[l*1024 + j - 1024];
    }
}

// ---------------- 128-row-tile GEMM, 2x4 warp grid, 4 stages ------------------
// MODE: 0 = fp32 out, 1 = fp16 out, 2 = fp16 out + relu.  TERMS: A terms.
template<int TERMS>
__device__ __forceinline__ void load_stage(uint32_t stb,
        const hf* __restrict__ Ahp, const hf* __restrict__ Alp, int lda,
        const hf* __restrict__ Bp, int ldb,
        int k0, int tid) {
    const uint32_t BOFF = (TERMS == 2) ? 16384u : 8192u;
    {
        int r0 = tid >> 2, c0 = tid & 3;
        const hf* a = Ahp + k0 + c0 * 8;
        #pragma unroll
        for (int h2 = 0; h2 < 2; h2++) {
            int row = r0 + h2 * 64;
            uint32_t d = stb + row * 64 + ((c0 ^ (row & 3)) << 4);
            cp16(d, a + (size_t)row * lda);
        }
        if (TERMS == 2) {
            const hf* a2 = Alp + k0 + c0 * 8;
            #pragma unroll
            for (int h2 = 0; h2 < 2; h2++) {
                int row = r0 + h2 * 64;
                uint32_t d = stb + 8192 + row * 64 + ((c0 ^ (row & 3)) << 4);
                cp16(d, a2 + (size_t)row * lda);
            }
        }
    }
    {
        int r0 = tid >> 4, c = tid & 15;
        const hf* b = Bp + c * 8;
        #pragma unroll
        for (int h2 = 0; h2 < 2; h2++) {
            int r = r0 + h2 * 16;
            uint32_t d = stb + BOFF + r * 256 + ((c ^ (r & 7)) << 4);
            cp16(d, b + (size_t)(k0 + r) * ldb);
        }
    }
    cp_commit();
}

template<int MODE, int TERMS>
__global__ __launch_bounds__(256)
void mma_gemm(const hf* __restrict__ Ah, const hf* __restrict__ Al,
              const hf* __restrict__ B,
              const float* __restrict__ bias,
              float* __restrict__ C, hf* __restrict__ Chi,
              int M, int N, int K, int ldb, int ldc)
{
    extern __shared__ char smem[];
    const uint32_t SSZ  = (TERMS == 2) ? 24576u : 16384u;
    const uint32_t BOFF = (TERMS == 2) ? 16384u : 8192u;
    uint32_t sbase = (uint32_t)__cvta_generic_to_shared(smem);
    int tid = threadIdx.x, lane = tid & 31, wid = tid >> 5;
    int wm = wid & 1, wn = wid >> 1;           // 2 (M) x 4 (N) warp grid
    int bm = blockIdx.x * 128, bn = blockIdx.y * 128;

    const hf* pAh = Ah + (size_t)bm * K;
    const hf* pAl = Al + (size_t)bm * K;
    const hf* pB  = B + bn;

    float acc[4][4][4];
    #pragma unroll
    for (int a = 0; a < 4; a++)
        #pragma unroll
        for (int b2 = 0; b2 < 4; b2++)
            #pragma unroll
            for (int d = 0; d < 4; d++) acc[a][b2][d] = 0.f;

    const int NCH = K >> 5;
    load_stage<TERMS>(sbase,           pAh, pAl, K, pB, ldb, 0,  tid);
    load_stage<TERMS>(sbase + SSZ,     pAh, pAl, K, pB, ldb, 32, tid);
    load_stage<TERMS>(sbase + 2 * SSZ, pAh, pAl, K, pB, ldb, 64, tid);

    int a_r  = wm * 64 + (lane & 15);
    int a_ck = (lane >> 4) & 1;
    int b_rr = ((lane >> 3) & 1) * 8 + (lane & 7);
    int b_cc = wn * 4 + (lane >> 4);

    for (int c = 0; c < NCH; c++) {
        cp_waitg(NCH - c);
        __syncthreads();
        if (c + 3 < NCH)
            load_stage<TERMS>(sbase + ((c + 3) & 3) * SSZ, pAh, pAl, K, pB, ldb,
                              (c + 3) << 5, tid);

        uint32_t stb = sbase + (c & 3) * SSZ;
        #pragma unroll
        for (int k16 = 0; k16 < 2; k16++) {
            uint32_t a_hi[4][4], a_lo[4][4];
            #pragma unroll
            for (int mf = 0; mf < 4; mf++) {
                int row = a_r + mf * 16;
                int ck  = k16 * 2 + a_ck;
                uint32_t addr = stb + row * 64 + ((ck ^ (row & 3)) << 4);
                ldsm4(a_hi[mf], addr);
                if (TERMS == 2) ldsm4(a_lo[mf], addr + 8192);
            }
            int rr = k16 * 16 + b_rr;
            #pragma unroll
            for (int np2 = 0; np2 < 2; np2++) {
                int cc = b_cc + np2 * 2;
                uint32_t addr = stb + BOFF + rr * 256 + ((cc ^ (rr & 7)) << 4);
                uint32_t bv[4];
                ldsm4t(bv, addr);
                #pragma unroll
                for (int mf = 0; mf < 4; mf++) {
                    mma16816(acc[mf][np2*2],   a_hi[mf], bv);
                    mma16816(acc[mf][np2*2+1], a_hi[mf], bv + 2);
                    if (TERMS == 2) {
                        mma16816(acc[mf][np2*2],   a_lo[mf], bv);
                        mma16816(acc[mf][np2*2+1], a_lo[mf], bv + 2);
                    }
                }
            }
        }
    }

    __syncthreads();

    #pragma unroll
    for (int mf = 0; mf < 4; mf++) {
        int row0 = bm + wm * 64 + mf * 16 + (lane >> 2);
        #pragma unroll
        for (int nf = 0; nf < 4; nf++) {
            int col = bn + wn * 32 + nf * 8 + ((lane & 3) << 1);
            float bb0 = bias[col], bb1 = bias[col + 1];
            float v0 = acc[mf][nf][0] + bb0, v1 = acc[mf][nf][1] + bb1;
            float v2 = acc[mf][nf][2] + bb0, v3 = acc[mf][nf][3] + bb1;
            if (MODE == 2) {
                v0 = fmaxf(v0, 0.f); v1 = fmaxf(v1, 0.f);
                v2 = fmaxf(v2, 0.f); v3 = fmaxf(v3, 0.f);
            }
            if (MODE == 0) {
                float2 o0; o0.x = v0; o0.y = v1;
                float2 o1; o1.x = v2; o1.y = v3;
                *(float2*)(C + (size_t)row0 * ldc + col) = o0;
                *(float2*)(C + (size_t)(row0 + 8) * ldc + col) = o1;
            } else {
                *(__half2*)(Chi + (size_t)row0 * ldc + col) =
                    __floats2half2_rn(v0, v1);
                *(__half2*)(Chi + (size_t)(row0 + 8) * ldc + col) =
                    __floats2half2_rn(v2, v3);
            }
        }
    }
}

#define GEMM_SMEM2 (4*24576)
#define GEMM_SMEM1 (4*16384)

// ---------------- 64-row-tile GEMM, 4 stages ----------------------------------
template<int TERMS>
__device__ __forceinline__ void load_stage64(uint32_t stb,
        const hf* __restrict__ Ahp, const hf* __restrict__ Alp, int lda,
        const hf* __restrict__ Bp, int ldb,
        int k0, int tid) {
    const uint32_t BOFF = (TERMS == 2) ? 8192u : 4096u;
    {
        int r0 = tid >> 2, c0 = tid & 3;
        uint32_t d = stb + r0 * 64 + ((c0 ^ (r0 & 3)) << 4);
        cp16(d, Ahp + k0 + c0 * 8 + (size_t)r0 * lda);
        if (TERMS == 2)
            cp16(d + 4096, Alp + k0 + c0 * 8 + (size_t)r0 * lda);
    }
    {
        int r0 = tid >> 4, c = tid & 15;
        const hf* b = Bp + c * 8;
        #pragma unroll
        for (int h2 = 0; h2 < 2; h2++) {
            int r = r0 + h2 * 16;
            uint32_t d = stb + BOFF + r * 256 + ((c ^ (r & 7)) << 4);
            cp16(d, b + (size_t)(k0 + r) * ldb);
        }
    }
    cp_commit();
}

template<int MODE, int TERMS>
__global__ __launch_bounds__(256)
void mma_gemm64(const hf* __restrict__ Ah, const hf* __restrict__ Al,
                const hf* __restrict__ B,
                const float* __restrict__ bias,
                float* __restrict__ C, hf* __restrict__ Chi,
                int M, int N, int K, int ldb, int ldc)
{
    extern __shared__ char smem[];
    const uint32_t SSZ  = (TERMS == 2) ? 16384u : 12288u;
    const uint32_t BOFF = (TERMS == 2) ? 8192u  : 4096u;
    uint32_t sbase = (uint32_t)__cvta_generic_to_shared(smem);
    int tid = threadIdx.x, lane = tid & 31, wid = tid >> 5;
    int wm = wid & 1, wn = wid >> 1;
    int bm = blockIdx.x * 64, bn = blockIdx.y * 128;

    const hf* pAh = Ah + (size_t)bm * K;
    const hf* pAl = Al + (size_t)bm * K;
    const hf* pB  = B + bn;

    float acc[2][4][4];
    #pragma unroll
    for (int a = 0; a < 2; a++)
        #pragma unroll
        for (int b2 = 0; b2 < 4; b2++)
            #pragma unroll
            for (int d = 0; d < 4; d++) acc[a][b2][d] = 0.f;

    const int NCH = K >> 5;
    load_stage64<TERMS>(sbase,           pAh, pAl, K, pB, ldb, 0,  tid);
    load_stage64<TERMS>(sbase + SSZ,     pAh, pAl, K, pB, ldb, 32, tid);
    load_stage64<TERMS>(sbase + 2 * SSZ, pAh, pAl, K, pB, ldb, 64, tid);

    int a_r  = wm * 32 + (lane & 15);
    int a_ck = (lane >> 4) & 1;
    int b_rr = ((lane >> 3) & 1) * 8 + (lane & 7);
    int b_cc = wn * 4 + (lane >> 4);

    for (int c = 0; c < NCH; c++) {
        cp_waitg(NCH - c);
        __syncthreads();
        if (c + 3 < NCH)
            load_stage64<TERMS>(sbase + ((c + 3) & 3) * SSZ, pAh, pAl, K, pB, ldb,
                                (c + 3) << 5, tid);

        uint32_t stb = sbase + (c & 3) * SSZ;
        #pragma unroll
        for (int k16 = 0; k16 < 2; k16++) {
            uint32_t a_hi[2][4], a_lo[2][4];
            #pragma unroll
            for (int mf = 0; mf < 2; mf++) {
                int row = a_r + mf * 16;
                int ck  = k16 * 2 + a_ck;
                uint32_t addr = stb + row * 64 + ((ck ^ (row & 3)) << 4);
                ldsm4(a_hi[mf], addr);
                if (TERMS == 2) ldsm4(a_lo[mf], addr + 4096);
            }
            int rr = k16 * 16 + b_rr;
            #pragma unroll
            for (int np2 = 0; np2 < 2; np2++) {
                int cc = b_cc + np2 * 2;
                uint32_t addr = stb + BOFF + rr * 256 + ((cc ^ (rr & 7)) << 4);
                uint32_t bv[4];
                ldsm4t(bv, addr);
                #pragma unroll
                for (int mf = 0; mf < 2; mf++) {
                    mma16816(acc[mf][np2*2],   a_hi[mf], bv);
                    mma16816(acc[mf][np2*2+1], a_hi[mf], bv + 2);
                    if (TERMS == 2) {
                        mma16816(acc[mf][np2*2],   a_lo[mf], bv);
                        mma16816(acc[mf][np2*2+1], a_lo[mf], bv + 2);
                    }
                }
            }
        }
    }

    __syncthreads();

    #pragma unroll
    for (int mf = 0; mf < 2; mf++) {
        int row0 = bm + wm * 32 + mf * 16 + (lane >> 2);
        #pragma unroll
        for (int nf = 0; nf < 4; nf++) {
            int col = bn + wn * 32 + nf * 8 + ((lane & 3) << 1);
            float bb0 = bias[col], bb1 = bias[col + 1];
            float v0 = acc[mf][nf][0] + bb0, v1 = acc[mf][nf][1] + bb1;
            float v2 = acc[mf][nf][2] + bb0, v3 = acc[mf][nf][3] + bb1;
            if (MODE == 0) {
                float2 o0; o0.x = v0; o0.y = v1;
                float2 o1; o1.x = v2; o1.y = v3;
                *(float2*)(C + (size_t)row0 * ldc + col) = o0;
                *(float2*)(C + (size_t)(row0 + 8) * ldc + col) = o1;
            } else {
                *(__half2*)(Chi + (size_t)row0 * ldc + col) =
                    __floats2half2_rn(v0, v1);
                *(__half2*)(Chi + (size_t)(row0 + 8) * ldc + col) =
                    __floats2half2_rn(v2, v3);
            }
        }
    }
}

#define GEMM_SMEM64_2 (4*16384)
#define GEMM_SMEM64_1 (4*12288)

// ---------------- flash attention (fp16 single-term, hi-only out) -------------
// smem: Q@0 16KB | K@16384 8KB | V@24576 8KB
#define FLASH_SMEM 32768

template<bool CAUSAL>
__global__ __launch_bounds__(256)
void flash_attn(const hf* __restrict__ Qh, int ldq, int qoff,
                const hf* __restrict__ Ks, int ldk, int koff,
                const hf* __restrict__ Vs, int ldv, int voff,
                const int* __restrict__ tgt,
                hf* __restrict__ Oh, int ldo,
                int Sq, int Sk)
{
    extern __shared__ char sm[];
    uint32_t sb = (uint32_t)__cvta_generic_to_shared(sm);
    int tid = threadIdx.x, lane = tid & 31, w = tid >> 5;
    int bh = blockIdx.y, b = bh >> 4, h = bh & 15;
    int q0 = (CAUSAL ? (gridDim.x - 1 - blockIdx.x) : blockIdx.x) * 128;

    {
        const hf* qh = Qh + (size_t)(b * Sq + q0) * ldq + qoff + h * 64;
        #pragma unroll
        for (int i = 0; i < 4; i++) {
            int idx = tid + i * 256;
            int row = idx >> 3, c = idx & 7;
            uint32_t off = row * 128 + ((c ^ (row & 7)) << 4);
            *(uint4*)(sm + off) = *(const uint4*)(qh + (size_t)row * ldq + c * 8);
        }
    }

    int rq = lane >> 2;
    int qrow0 = q0 + w * 16 + rq;
    int qrow1 = qrow0 + 8;
    bool pad0 = false, pad1 = false;
    if (CAUSAL) {
        pad0 = (tgt[b * Sq + qrow0] == 0);
        pad1 = (tgt[b * Sq + qrow1] == 0);
    }

    float O[8][4];
    #pragma unroll
    for (int i = 0; i < 8; i++)
        #pragma unroll
        for (int j = 0; j < 4; j++) O[i][j] = 0.f;
    float m0 = -1e30f, m1 = -1e30f, s0 = 0.f, s1 = 0.f;

    int kend = CAUSAL ? (q0 + 128) : Sk;

    for (int k0 = 0; k0 < kend; k0 += 64) {
        __syncthreads();
        {
            const hf* srcs[2] = {
                Ks + (size_t)(b * Sk + k0) * ldk + koff + h * 64,
                Vs + (size_t)(b * Sk + k0) * ldv + voff + h * 64 };
            int lds[2] = { ldk, ldv };
            uint32_t dsts[2] = { 16384u, 24576u };
            #pragma unroll
            for (int t = 0; t < 2; t++) {
                #pragma unroll
                for (int i = 0; i < 2; i++) {
                    int idx = tid + i * 256;
                    int row = idx >> 3, c = idx & 7;
                    *(uint4*)(sm + dsts[t] + row * 128 + ((c ^ (row & 7)) << 4)) =
                        *(const uint4*)(srcs[t] + (size_t)row * lds[t] + c * 8);
                }
            }
        }
        __syncthreads();

        float S[8][4];
        #pragma unroll
        for (int i = 0; i < 8; i++)
            #pragma unroll
            for (int j = 0; j < 4; j++) S[i][j] = 0.f;

        #pragma unroll
        for (int ks = 0; ks < 4; ks++) {
            int arow = w * 16 + (lane & 15);
            int ac = ks * 2 + ((lane >> 4) & 1);
            uint32_t qa = sb + arow * 128 + ((ac ^ (arow & 7)) << 4);
            uint32_t ah[4];
            ldsm4(ah, qa);
            #pragma unroll
            for (int np = 0; np < 4; np++) {
                int brow = np * 16 + (lane & 7) + ((lane >> 4) & 1) * 8;
                int bc = ks * 2 + ((lane >> 3) & 1);
                uint32_t ka = sb + 16384 + brow * 128 + ((bc ^ (brow & 7)) << 4);
                uint32_t kb[4];
                ldsm4(kb, ka);
                mma16816(S[np*2],   ah, kb);     mma16816(S[np*2+1],   ah, kb + 2);
            }
        }

        #pragma unroll
        for (int nt = 0; nt < 8; nt++) {
            int col = k0 + nt * 8 + 2 * (lane & 3);
            #pragma unroll
            for (int e = 0; e < 4; e++) S[nt][e] *= 0.125f;
            if (CAUSAL && k0 >= q0) {
                if (col     > qrow0) S[nt][0] = -1e9f;
                if (col + 1 > qrow0) S[nt][1] = -1e9f;
                if (col     > qrow1) S[nt][2] = -1e9f;
                if (col + 1 > qrow1) S[nt][3] = -1e9f;
            }
            if (CAUSAL) {
                if (pad0) { S[nt][0] = -1e9f; S[nt][1] = -1e9f; }
                if (pad1) { S[nt][2] = -1e9f; S[nt][3] = -1e9f; }
            }
        }

        float mx0 = -1e30f, mx1 = -1e30f;
        #pragma unroll
        for (int nt = 0; nt < 8; nt++) {
            mx0 = fmaxf(mx0, fmaxf(S[nt][0], S[nt][1]));
            mx1 = fmaxf(mx1, fmaxf(S[nt][2], S[nt][3]));
        }
        mx0 = fmaxf(mx0, __shfl_xor_sync(0xffffffffu, mx0, 1));
        mx0 = fmaxf(mx0, __shfl_xor_sync(0xffffffffu, mx0, 2));
        mx1 = fmaxf(mx1, __shfl_xor_sync(0xffffffffu, mx1, 1));
        mx1 = fmaxf(mx1, __shfl_xor_sync(0xffffffffu, mx1, 2));
        float mn0 = fmaxf(m0, mx0), mn1 = fmaxf(m1, mx1);
        float al0 = __expf(m0 - mn0), al1 = __expf(m1 - mn1);
        m0 = mn0; m1 = mn1;
        float ps0 = 0.f, ps1 = 0.f;
        #pragma unroll
        for (int nt = 0; nt < 8; nt++) {
            S[nt][0] = __expf(S[nt][0] - mn0);
            S[nt][1] = __expf(S[nt][1] - mn0);
            S[nt][2] = __expf(S[nt][2] - mn1);
            S[nt][3] = __expf(S[nt][3] - mn1);
            ps0 += S[nt][0] + S[nt][1];
            ps1 += S[nt][2] + S[nt][3];
        }
        ps0 += __shfl_xor_sync(0xffffffffu, ps0, 1);
        ps0 += __shfl_xor_sync(0xffffffffu, ps0, 2);
        ps1 += __shfl_xor_sync(0xffffffffu, ps1, 1);
        ps1 += __shfl_xor_sync(0xffffffffu, ps1, 2);
        s0 = s0 * al0 + ps0;
        s1 = s1 * al1 + ps1;
        #pragma unroll
        for (int nt = 0; nt < 8; nt++) {
            O[nt][0] *= al0; O[nt][1] *= al0;
            O[nt][2] *= al1; O[nt][3] *= al1;
        }

        #pragma unroll
        for (int ks = 0; ks < 4; ks++) {
            uint32_t pah[4];
            #pragma unroll
            for (int half = 0; half < 2; half++) {
                pah[half*2 + 0] = pkh(__float2half_rn(S[2*ks+half][0]),
                                      __float2half_rn(S[2*ks+half][1]));
                pah[half*2 + 1] = pkh(__float2half_rn(S[2*ks+half][2]),
                                      __float2half_rn(S[2*ks+half][3]));
            }
            #pragma unroll
            for (int np = 0; np < 4; np++) {
                int rr = ks * 16 + ((lane >> 3) & 1) * 8 + (lane & 7);
                int cc = np * 2 + (lane >> 4);
                uint32_t va = sb + 24576 + rr * 128 + ((cc ^ (rr & 7)) << 4);
                uint32_t vb[4];
                ldsm4t(vb, va);
                mma16816(O[np*2],   pah, vb);     mma16816(O[np*2+1],   pah, vb + 2);
            }
        }
    }

    float inv0 = 1.f / s0, inv1 = 1.f / s1;
    size_t tr0 = (size_t)(b * Sq + qrow0) * ldo;
    size_t tr1 = (size_t)(b * Sq + qrow1) * ldo;
    #pragma unroll
    for (int nt = 0; nt < 8; nt++) {
        int col = h * 64 + nt * 8 + 2 * (lane & 3);
        *(__half2*)(Oh + tr0 + col) = __floats2half2_rn(O[nt][0] * inv0, O[nt][1] * inv0);
        *(__half2*)(Oh + tr1 + col) = __floats2half2_rn(O[nt][2] * inv1, O[nt][3] * inv1);
    }
}

// ---------------- positional encoding / embed --------------------------------
__device__ __forceinline__ float pe_val(int s, int d) {
    const float c = -0.0089944730195079f;
    int i2 = d & ~1;
    float freq = expf((float)i2 * c);
    float ang  = (float)s * freq;
    return (d & 1) ? cosf(ang) : sinf(ang);
}

__global__ void embed_pe(const int* __restrict__ tgt, const float* __restrict__ emb,
                         float* __restrict__ X, hf* __restrict__ Xh, hf* __restrict__ Xl) {
    int row = blockIdx.x;
    int s   = row % TGT;
    int tok = tgt[row];
    int t   = threadIdx.x;
    #pragma unroll
    for (int i = 0; i < 4; i++) {
        int d = t * 4 + i;
        float v = emb[(size_t)tok * D_MODEL + d] + pe_val(s, d);
        X[(size_t)row * D_MODEL + d] = v;
        hf h = __float2half_rn(v);
        Xh[(size_t)row * D_MODEL + d] = h;
        Xl[(size_t)row * D_MODEL + d] = __float2half_rn(v - __half2float(h));
    }
}

__global__ void src_pe(const float* __restrict__ src,
                       hf* __restrict__ Eh, hf* __restrict__ El) {
    int row = blockIdx.x;
    int s   = row % SRCL;
    int t   = threadIdx.x;
    #pragma unroll
    for (int i = 0; i < 4; i++) {
        int d = t * 4 + i;
        float v = src[(size_t)row * D_MODEL + d] + pe_val(s, d);
        hf h = __float2half_rn(v);
        Eh[(size_t)row * D_MODEL + d] = h;
        El[(size_t)row * D_MODEL + d] = __float2half_rn(v - __half2float(h));
    }
}

// ---------------- add + LayerNorm --------------------------------------------
__global__ __launch_bounds__(256) void add_ln(
    const float* __restrict__ X, const float* __restrict__ A,
    const float* __restrict__ G, const float* __restrict__ Bt,
    float* __restrict__ Y, hf* __restrict__ Yh, hf* __restrict__ Yl)
{
    __shared__ float red[8];
    __shared__ float bcast;
    int row = blockIdx.x;
    int t = threadIdx.x;
    int lane = t & 31, wid = t >> 5;

    float4 xv = *(const float4*)(X + (size_t)row * D_MODEL + t * 4);
    float4 av = *(const float4*)(A + (size_t)row * D_MODEL + t * 4);
    float v0 = xv.x + av.x, v1 = xv.y + av.y, v2 = xv.z + av.z, v3 = xv.w + av.w;

    float s = v0 + v1 + v2 + v3;
    #pragma unroll
    for (int o = 16; o; o >>= 1) s += __shfl_xor_sync(0xffffffffu, s, o);
    if (lane == 0) red[wid] = s;
    __syncthreads();
    if (t == 0) {
        float tot = 0.f;
        #pragma unroll
        for (int i = 0; i < 8; i++) tot += red[i];
        bcast = tot;
    }
    __syncthreads();
    float mean = bcast * (1.f / 1024.f);

    float d0 = v0 - mean, d1 = v1 - mean, d2 = v2 - mean, d3 = v3 - mean;
    s = d0 * d0 + d1 * d1 + d2 * d2 + d3 * d3;
    #pragma unroll
    for (int o = 16; o; o >>= 1) s += __shfl_xor_sync(0xffffffffu, s, o);
    if (lane == 0) red[wid] = s;
    __syncthreads();
    if (t == 0) {
        float tot = 0.f;
        #pragma unroll
        for (int i = 0; i < 8; i++) tot += red[i];
        bcast = tot;
    }
    __syncthreads();
    float rstd = rsqrtf(bcast * (1.f / 1024.f) + 1e-5f);

    int c = t * 4;
    float o0 = d0 * rstd * G[c + 0] + Bt[c + 0];
    float o1 = d1 * rstd * G[c + 1] + Bt[c + 1];
    float o2 = d2 * rstd * G[c + 2] + Bt[c + 2];
    float o3 = d3 * rstd * G[c + 3] + Bt[c + 3];
    float4 o; o.x = o0; o.y = o1; o.z = o2; o.w = o3;
    *(float4*)(Y + (size_t)row * D_MODEL + c) = o;
    hf h0 = __float2half_rn(o0), h1 = __float2half_rn(o1);
    hf h2 = __float2half_rn(o2), h3 = __float2half_rn(o3);
    *(__half2*)(Yh + (size_t)row * D_MODEL + c)     = __halves2half2(h0, h1);
    *(__half2*)(Yh + (size_t)row * D_MODEL + c + 2) = __halves2half2(h2, h3);
    *(__half2*)(Yl + (size_t)row * D_MODEL + c) =
        __floats2half2_rn(o0 - __half2float(h0), o1 - __half2float(h1));
    *(__half2*)(Yl + (size_t)row * D_MODEL + c + 2) =
        __floats2half2_rn(o2 - __half2float(h2), o3 - __half2float(h3));
}

// ---------------- host pointers ----------------------------------------------
static hf *h_xhi, *h_xlo, *h_ehi, *h_elo, *h_qkvh, *h_kvh, *h_ahi, *h_w;
static float *h_x, *h_tmp, *h_bias;

// ---------------- orchestration ----------------------------------------------
extern "C" void kernel_launch(void* const* d_in, const int* in_sizes, int n_in,
                              void* d_out, int out_size) {
    bool layoutA = (in_sizes[3] == 8 * 1024 * 1024);

    const float* src = (const float*)d_in[0];
    const int*   tgt = (const int*)  d_in[1];
    const float* emb = (const float*)d_in[2];

    const float *sa_wq, *sa_bq, *sa_wk, *sa_bk, *sa_wv, *sa_bv, *sa_wo, *sa_bo;
    const float *ca_wq, *ca_bq, *ca_wk, *ca_bk, *ca_wv, *ca_bv, *ca_wo, *ca_bo;
    const float *w1, *b1, *w2, *b2;
    const float *n1g, *n1b, *n2g, *n2b, *n3g, *n3b;
    const float *fc_w, *fc_b;

    if (layoutA) {
        sa_wq = (const float*)d_in[3];  sa_bq = (const float*)d_in[4];
        sa_wk = (const float*)d_in[5];  sa_bk = (const float*)d_in[6];
        sa_wv = (const float*)d_in[7];  sa_bv = (const float*)d_in[8];
        sa_wo = (const float*)d_in[9];  sa_bo = (const float*)d_in[10];
        ca_wq = (const float*)d_in[11]; ca_bq = (const float*)d_in[12];
        ca_wk = (const float*)d_in[13]; ca_bk = (const float*)d_in[14];
        ca_wv = (const float*)d_in[15]; ca_bv = (const float*)d_in[16];
        ca_wo = (const float*)d_in[17]; ca_bo = (const float*)d_in[18];
        w1 = (const float*)d_in[19]; b1 = (const float*)d_in[20];
        w2 = (const float*)d_in[21]; b2 = (const float*)d_in[22];
        n1g = (const float*)d_in[23]; n1b = (const float*)d_in[24];
        n2g = (const float*)d_in[25]; n2b = (const float*)d_in[26];
        n3g = (const float*)d_in[27]; n3b = (const float*)d_in[28];
        fc_w = (const float*)d_in[29]; fc_b = (const float*)d_in[30];
    } else {
        fc_w = (const float*)d_in[3];  fc_b = (const float*)d_in[4];
        sa_wq = (const float*)d_in[5];  sa_bq = (const float*)d_in[6];
        sa_wk = (const float*)d_in[7];  sa_bk = (const float*)d_in[8];
        sa_wv = (const float*)d_in[9];  sa_bv = (const float*)d_in[10];
        sa_wo = (const float*)d_in[11]; sa_bo = (const float*)d_in[12];
        ca_wq = (const float*)d_in[13]; ca_bq = (const float*)d_in[14];
        ca_wk = (const float*)d_in[15]; ca_bk = (const float*)d_in[16];
        ca_wv = (const float*)d_in[17]; ca_bv = (const float*)d_in[18];
        ca_wo = (const float*)d_in[19]; ca_bo = (const float*)d_in[20];
        w1 = (const float*)d_in[21]; b1 = (const float*)d_in[22];
        w2 = (const float*)d_in[23]; b2 = (const float*)d_in[24];
        n1g = (const float*)d_in[25]; n2g = (const float*)d_in[26];
        n3g = (const float*)d_in[27]; n1b = (const float*)d_in[28];
        n2b = (const float*)d_in[29]; n3b = (const float*)d_in[30];
    }

    cudaGetSymbolAddress((void**)&h_x,    g_x);
    cudaGetSymbolAddress((void**)&h_tmp,  g_tmp);
    cudaGetSymbolAddress((void**)&h_xhi,  g_xhi);
    cudaGetSymbolAddress((void**)&h_xlo,  g_xlo);
    cudaGetSymbolAddress((void**)&h_ehi,  g_ehi);
    cudaGetSymbolAddress((void**)&h_elo,  g_elo);
    cudaGetSymbolAddress((void**)&h_qkvh, g_qkvh);
    cudaGetSymbolAddress((void**)&h_kvh,  g_kvh);
    cudaGetSymbolAddress((void**)&h_ahi,  g_ahi);
    cudaGetSymbolAddress((void**)&h_w,    g_w);
    cudaGetSymbolAddress((void**)&h_bias, g_biasall);

    cudaFuncSetAttribute((const void*)mma_gemm<1,2>, cudaFuncAttributeMaxDynamicSharedMemorySize, GEMM_SMEM2);
    cudaFuncSetAttribute((const void*)mma_gemm<2,2>, cudaFuncAttributeMaxDynamicSharedMemorySize, GEMM_SMEM2);
    cudaFuncSetAttribute((const void*)mma_gemm<0,1>, cudaFuncAttributeMaxDynamicSharedMemorySize, GEMM_SMEM1);
    cudaFuncSetAttribute((const void*)mma_gemm64<0,1>, cudaFuncAttributeMaxDynamicSharedMemorySize, GEMM_SMEM64_1);
    cudaFuncSetAttribute((const void*)mma_gemm64<1,2>, cudaFuncAttributeMaxDynamicSharedMemorySize, GEMM_SMEM64_2);
    cudaFuncSetAttribute((const void*)flash_attn<true>,  cudaFuncAttributeMaxDynamicSharedMemorySize, FLASH_SMEM);
    cudaFuncSetAttribute((const void*)flash_attn<false>, cudaFuncAttributeMaxDynamicSharedMemorySize, FLASH_SMEM);

    const int Mx = NB * TGT;    // 2048
    const int Me = NB * SRCL;   // 1024

    {
        ConvDescs D;
        const long C2 = 2097152, C8 = 8388608;
        const float* srcs[11] = { sa_wq, sa_wk, sa_wv, sa_wo, ca_wq,
                                  ca_wk, ca_wv, ca_wo, w1, w2, fc_w };
        long starts[11] = { 0, C2, 2*C2, 3*C2, 4*C2, 5*C2, 6*C2, 7*C2,
                            8*C2, 8*C2 + C8, 8*C2 + 2*C8 };
        size_t dsts[11] = { OFF_QKV, OFF_QKV, OFF_QKV, OFF_SAO, OFF_CAQ,
                            OFF_CAKV, OFF_CAKV, OFF_CAO, OFF_FF1, OFF_FF2, OFF_FC };
        int modes[11] = { 1, 1, 1, 0, 0, 2, 2, 0, 0, 0, 0 };
        int offs[11]  = { 0, 1024, 2048, 0, 0, 0, 1024, 0, 0, 0, 0 };
        for (int i = 0; i < 11; i++) {
            D.src[i] = srcs[i]; D.start4[i] = starts[i];
            D.dst[i] = dsts[i]; D.mode[i] = modes[i]; D.off[i] = offs[i];
        }
        long total4 = 8*C2 + 2*C8 + 8192000;
        conv_all<<<4096, 256>>>(D, h_w, total4);
    }
    bias_all<<<160, 256>>>(sa_bq, sa_bk, sa_bv, ca_bk, ca_bv, h_bias);
    embed_pe<<<Mx, 256>>>(tgt, emb, h_x, h_xhi, h_xlo);

    bool did_src = false;

    for (int l = 0; l < NLAYER; l++) {
        const hf* Wqkv = h_w + OFF_QKV  + (size_t)l * 3145728;
        const hf* Wsao = h_w + OFF_SAO  + (size_t)l * 1048576;
        const hf* Wcaq = h_w + OFF_CAQ  + (size_t)l * 1048576;
        const hf* Wkv  = h_w + OFF_CAKV + (size_t)l * 2097152;
        const hf* Wcao = h_w + OFF_CAO  + (size_t)l * 1048576;
        const hf* Wf1  = h_w + OFF_FF1  + (size_t)l * 4194304;
        const hf* Wf2  = h_w + OFF_FF2  + (size_t)l * 4194304;

        // ---- self-attention ----
        mma_gemm<1,2><<<dim3(16, 24), 256, GEMM_SMEM2>>>(h_xhi, h_xlo, Wqkv,
            h_bias + (size_t)l * 3072, (float*)0, h_qkvh, Mx, 3072, D_MODEL, 3072, 3072);
        if (!did_src) { src_pe<<<Me, 256>>>(src, h_ehi, h_elo); did_src = true; }
        flash_attn<true><<<dim3(4, 64), 256, FLASH_SMEM>>>(
            h_qkvh, 3072, 0, h_qkvh, 3072, 1024,
            h_qkvh, 3072, 2048, tgt, h_ahi, 1024, TGT, TGT);
        mma_gemm64<0,1><<<dim3(32, 8), 256, GEMM_SMEM64_1>>>(h_ahi, h_ahi, Wsao,
            sa_bo + l*D_MODEL, h_tmp, (hf*)0, Mx, D_MODEL, D_MODEL, D_MODEL, D_MODEL);
        add_ln<<<Mx, 256>>>(h_x, h_tmp, n1g + l*D_MODEL, n1b + l*D_MODEL, h_x, h_xhi, h_xlo);

        // ---- cross-attention ----
        mma_gemm64<1,2><<<dim3(32, 8), 256, GEMM_SMEM64_2>>>(h_xhi, h_xlo, Wcaq,
            ca_bq + l*D_MODEL, (float*)0, h_qkvh, Mx, D_MODEL, D_MODEL, D_MODEL, D_MODEL);
        mma_gemm64<1,2><<<dim3(16, 16), 256, GEMM_SMEM64_2>>>(h_ehi, h_elo, Wkv,
            h_bias + NLAYER*3072 + (size_t)l * 2048, (float*)0, h_kvh, Me, 2048, D_MODEL, 2048, 2048);
        flash_attn<false><<<dim3(4, 64), 256, FLASH_SMEM>>>(
            h_qkvh, 1024, 0, h_kvh, 2048, 0,
            h_kvh, 2048, 1024, (const int*)0, h_ahi, 1024, TGT, SRCL);
        mma_gemm64<0,1><<<dim3(32, 8), 256, GEMM_SMEM64_1>>>(h_ahi, h_ahi, Wcao,
            ca_bo + l*D_MODEL, h_tmp, (hf*)0, Mx, D_MODEL, D_MODEL, D_MODEL, D_MODEL);
        add_ln<<<Mx, 256>>>(h_x, h_tmp, n2g + l*D_MODEL, n2b + l*D_MODEL, h_x, h_xhi, h_xlo);

        // ---- FFN ----
        mma_gemm<2,2><<<dim3(16, 32), 256, GEMM_SMEM2>>>(h_xhi, h_xlo, Wf1,
            b1 + (size_t)l*FFDIM, (float*)0, h_ahi, Mx, FFDIM, D_MODEL, FFDIM, FFDIM);
        mma_gemm64<0,1><<<dim3(32, 8), 256, GEMM_SMEM64_1>>>(h_ahi, h_ahi, Wf2,
            b2 + (size_t)l*D_MODEL, h_tmp, (hf*)0, Mx, D_MODEL, FFDIM, D_MODEL, D_MODEL);
        add_ln<<<Mx, 256>>>(h_x, h_tmp, n3g + l*D_MODEL, n3b + l*D_MODEL, h_x, h_xhi, h_xlo);
    }

    // ---- final projection to vocab: single-term fp16 ----
    mma_gemm<0,1><<<dim3(16, 250), 256, GEMM_SMEM1>>>(h_xhi, h_xhi, h_w + OFF_FC,
        fc_b, (float*)d_out, (hf*)0, Mx, VOCAB, D_MODEL, VOCAB, VOCAB);
    (void)n_in; (void)out_size;
}